// round 15
// baseline (speedup 1.0000x reference)
#include <cuda_runtime.h>
#include <cuda_bf16.h>
#include <math.h>
#include <stdint.h>

#define NN 50000
#define NPAD 50048
#define EE 800000
#define ENT (EE + NN)
#define NH 8
#define PH 16
#define DH 128
#define D0 56
#define NC 7
#define NL 3
#define NB_SCAN 196  // ceil(50000/256)
#define KC0 90       // ceil(1433/16) k-chunks for gemm0

// packed fp32x2 FMA (sm_103a)
#define FFMA2(acc, h, w) \
    asm("fma.rn.f32x2 %0, %1, %2, %0;" : "+l"(acc) : "l"(h), "l"(w))
#define PACKW(dst, f) \
    asm("mov.b64 %0, {%1, %1};" : "=l"(dst) : "r"(__float_as_uint(f)))
#define UNPK(lo, hi, v) \
    do { unsigned int _a, _b; \
         asm("mov.b64 {%0,%1}, %2;" : "=r"(_a), "=r"(_b) : "l"(v)); \
         lo = __uint_as_float(_a); hi = __uint_as_float(_b); } while (0)

__device__ __forceinline__ uint32_t pkbf2(float hi, float lo) {
    uint32_t d;
    asm("cvt.rn.bf16x2.f32 %0, %1, %2;" : "=r"(d) : "f"(hi), "f"(lo));
    return d;
}
__device__ __forceinline__ float bfres(float v) {
    return v - __bfloat162float(__float2bfloat16(v));
}
__device__ __forceinline__ void mma16816(float* c, const uint32_t* a,
                                         uint32_t b0, uint32_t b1) {
    asm volatile(
        "mma.sync.aligned.m16n8k16.row.col.f32.bf16.bf16.f32 "
        "{%0,%1,%2,%3}, {%4,%5,%6,%7}, {%8,%9}, {%0,%1,%2,%3};"
        : "+f"(c[0]), "+f"(c[1]), "+f"(c[2]), "+f"(c[3])
        : "r"(a[0]), "r"(a[1]), "r"(a[2]), "r"(a[3]), "r"(b0), "r"(b1));
}
__device__ __forceinline__ void ldm_x4(uint32_t& r0, uint32_t& r1, uint32_t& r2,
                                       uint32_t& r3, uint32_t addr) {
    asm volatile("ldmatrix.sync.aligned.m8n8.x4.shared.b16 {%0,%1,%2,%3}, [%4];"
                 : "=r"(r0), "=r"(r1), "=r"(r2), "=r"(r3) : "r"(addr));
}

// ---------------- scratch ----------------
__device__ int   g_deg[NN];
__device__ int   g_off[NN + 1];
__device__ int   g_cur[NN];
__device__ int   g_part[256];
__device__ int   g_partoff[256];
__device__ int   g_srcs[ENT + 8];
__device__ float g_norm[ENT + 8];
__device__ float g_dinv[NN];
__device__ float g_nsum[NPAD];
__device__ float g_hB[NPAD * D0];
__device__ float g_hA[NPAD * PH];
__device__ float g_agg[NPAD * D0];
__device__ float g_x1[NPAD * D0];
__device__ float g_x2[NPAD * DH];
__device__ float2 g_esx[NPAD * NH];   // (exp(es), exp(0.2*es)) per node/head
__device__ float g_ed[NPAD * NH];
__device__ float g_bvec[2 * DH];
__device__ float g_fw[PH * NC];
__device__ float g_fb[NC];
__device__ uint4 g_wtf[9 * 8 * 16 * 32];  // GAT W frags: [li][kc][nt][lane]
__device__ uint4 g_wgf[9 * 16 * 32];      // GCN W frags (k=16): [li][nt][lane]
__device__ uint4 g_wff[KC0 * 7 * 32];     // w_feat frags: [kc][nt][lane]

// ---------------- CSR construction ----------------
__global__ void k_deg_init() {
    int i = blockIdx.x * blockDim.x + threadIdx.x;
    if (i < NN) g_deg[i] = 1;
    if (i < NPAD) g_nsum[i] = 0.f;
}

__global__ void k_deg_count(const int* __restrict__ ei) {
    int e = blockIdx.x * blockDim.x + threadIdx.x;
    if (e < EE) atomicAdd(&g_deg[ei[EE + e]], 1);
}

__global__ void k_scan1() {
    __shared__ int sh[256];
    int t = threadIdx.x;
    int i = blockIdx.x * 256 + t;
    int d = (i < NN) ? g_deg[i] : 0;
    sh[t] = d;
    __syncthreads();
#pragma unroll
    for (int off = 1; off < 256; off <<= 1) {
        int v = (t >= off) ? sh[t - off] : 0;
        __syncthreads();
        sh[t] += v;
        __syncthreads();
    }
    if (t == 255) g_part[blockIdx.x] = sh[255];
    if (i < NN) g_off[i] = sh[t] - d;
}

__global__ void k_scan2() {
    __shared__ int sh[256];
    int t = threadIdx.x;
    int v = (t < NB_SCAN) ? g_part[t] : 0;
    sh[t] = v;
    __syncthreads();
#pragma unroll
    for (int off = 1; off < 256; off <<= 1) {
        int u = (t >= off) ? sh[t - off] : 0;
        __syncthreads();
        sh[t] += u;
        __syncthreads();
    }
    g_partoff[t] = sh[t] - v;
}

__global__ void k_scan3() {
    int i = blockIdx.x * blockDim.x + threadIdx.x;
    if (i >= NN) return;
    int off = g_off[i] + g_partoff[i >> 8];
    g_off[i] = off;
    g_cur[i] = off;
    g_dinv[i] = rsqrtf((float)g_deg[i]);
    if (i == 0) g_off[NN] = ENT;
}

__global__ void k_fill(const int* __restrict__ ei) {
    int e = blockIdx.x * blockDim.x + threadIdx.x;
    if (e >= ENT) return;
    int s, d;
    if (e < EE) { s = ei[e]; d = ei[EE + e]; }
    else        { s = d = e - EE; }
    int p = atomicAdd(&g_cur[d], 1);
    float nm = g_dinv[s] * g_dinv[d];
    g_srcs[p] = s;
    g_norm[p] = nm;
    atomicAdd(&g_nsum[d], nm);
}

// ---------------- smem-free tensor-core GEMM0 (R11 proven version) -------------
__device__ __forceinline__ void g0_load(const float* xp1, const float* xp2,
                                        bool p1, bool p2, int kb, float* v) {
    v[0] = p1 ? xp1[kb]     : 0.f;
    v[1] = p1 ? xp1[kb + 1] : 0.f;
    v[2] = p1 ? xp1[kb + 8] : 0.f;
    v[3] = p1 ? xp1[kb + 9] : 0.f;
    v[4] = p2 ? xp2[kb]     : 0.f;
    v[5] = p2 ? xp2[kb + 1] : 0.f;
    v[6] = p2 ? xp2[kb + 8] : 0.f;
    v[7] = p2 ? xp2[kb + 9] : 0.f;
}
__device__ __forceinline__ void g0_mma(const float* v, const uint4* wp,
                                       float acc[7][4]) {
    uint32_t ah[4], al[4];
    ah[0] = pkbf2(v[1], v[0]); al[0] = pkbf2(bfres(v[1]), bfres(v[0]));
    ah[1] = pkbf2(v[5], v[4]); al[1] = pkbf2(bfres(v[5]), bfres(v[4]));
    ah[2] = pkbf2(v[3], v[2]); al[2] = pkbf2(bfres(v[3]), bfres(v[2]));
    ah[3] = pkbf2(v[7], v[6]); al[3] = pkbf2(bfres(v[7]), bfres(v[6]));
#pragma unroll
    for (int nt = 0; nt < 7; nt++) {
        uint4 b = wp[nt * 32];
        mma16816(acc[nt], ah, b.x, b.y);
        mma16816(acc[nt], ah, b.z, b.w);
        mma16816(acc[nt], al, b.x, b.y);
    }
}

__global__ __launch_bounds__(256)
void k_gemm0(const float* __restrict__ x) {
    int tid = threadIdx.x;
    int lane = tid & 31;
    int wid = tid >> 5;
    int row0 = blockIdx.x * 128;
    int r1 = row0 + wid * 16 + (lane >> 2);
    int r2 = r1 + 8;
    int kq = (lane & 3) * 2;
    bool p1 = r1 < NN, p2 = r2 < NN;
    const float* xp1 = x + (int64_t)r1 * 1433 + kq;
    const float* xp2 = x + (int64_t)r2 * 1433 + kq;

    float acc[7][4];
#pragma unroll
    for (int nt = 0; nt < 7; nt++)
        acc[nt][0] = acc[nt][1] = acc[nt][2] = acc[nt][3] = 0.f;

    const uint4* wbase = g_wff + lane;

    int kc = 0;
    for (; kc + 2 <= KC0 - 1; kc += 2) {
        float va[8], vb[8];
        g0_load(xp1, xp2, p1, p2, kc * 16, va);
        g0_load(xp1, xp2, p1, p2, kc * 16 + 16, vb);
        g0_mma(va, wbase + kc * 7 * 32, acc);
        g0_mma(vb, wbase + (kc + 1) * 7 * 32, acc);
    }
    {
        float va[8];
        g0_load(xp1, xp2, p1, p2, kc * 16, va);
        g0_mma(va, wbase + kc * 7 * 32, acc);
    }
    {
        const int kb = (KC0 - 1) * 16;
        float v[8];
        v[0] = p1 ? xp1[kb]     : 0.f;
        v[1] = p1 ? xp1[kb + 1] : 0.f;
        v[2] = (p1 && kq == 0) ? xp1[kb + 8] : 0.f;
        v[3] = 0.f;
        v[4] = p2 ? xp2[kb]     : 0.f;
        v[5] = p2 ? xp2[kb + 1] : 0.f;
        v[6] = (p2 && kq == 0) ? xp2[kb + 8] : 0.f;
        v[7] = 0.f;
        g0_mma(v, wbase + (KC0 - 1) * 7 * 32, acc);
    }

#pragma unroll
    for (int nt = 0; nt < 7; nt++) {
        int col = nt * 8 + kq;
        if (p1) *(float2*)&g_x1[r1 * 56 + col] = make_float2(acc[nt][0], acc[nt][1]);
        if (p2) *(float2*)&g_x1[r2 * 56 + col] = make_float2(acc[nt][2], acc[nt][3]);
    }
}

// ---------------- weight fragment swizzles (merged; + w_feat frags + out prep) --
__global__ void k_swz(const float* __restrict__ gat_w, const float* __restrict__ gcn_w,
                      const float* __restrict__ w_feat,
                      const float* __restrict__ masW2, const float* __restrict__ mas_b2,
                      const float* __restrict__ out_w, const float* __restrict__ out_b) {
    int idx = blockIdx.x * blockDim.x + threadIdx.x;
    if (idx < 9 * 8 * 128) {
        int li = idx >> 10;
        int rem = idx & 1023;
        int kc = rem >> 7;
        int n = rem & 127;
        const float* W = gat_w + li * 128 * 128;
        float wv[16], rv[16];
#pragma unroll
        for (int kk = 0; kk < 16; kk++) {
            float v = W[(kc * 16 + kk) * 128 + n];
            wv[kk] = v;
            rv[kk] = bfres(v);
        }
        int nt = n >> 3;
#pragma unroll
        for (int kp = 0; kp < 4; kp++) {
            int lane = (n & 7) * 4 + kp;
            uint4 o;
            o.x = pkbf2(wv[kp * 2 + 1], wv[kp * 2]);
            o.y = pkbf2(wv[kp * 2 + 9], wv[kp * 2 + 8]);
            o.z = pkbf2(rv[kp * 2 + 1], rv[kp * 2]);
            o.w = pkbf2(rv[kp * 2 + 9], rv[kp * 2 + 8]);
            g_wtf[((li * 8 + kc) * 16 + nt) * 32 + lane] = o;
        }
    } else if (idx < 9 * 8 * 128 + 6 * 128) {
        int id2 = idx - 9 * 8 * 128;
        int j = id2 >> 7;          // 0..5
        int n = id2 & 127;
        int m = j >> 1, i = 1 + (j & 1);
        int li = m * 3 + i;
        const float* W = gcn_w + (m * 2 + (i - 1)) * 16 * 128;
        float wv[16], rv[16];
#pragma unroll
        for (int kk = 0; kk < 16; kk++) {
            float v = W[kk * 128 + n];
            wv[kk] = v;
            rv[kk] = bfres(v);
        }
        int nt = n >> 3;
#pragma unroll
        for (int kp = 0; kp < 4; kp++) {
            int lane = (n & 7) * 4 + kp;
            uint4 o;
            o.x = pkbf2(wv[kp * 2 + 1], wv[kp * 2]);
            o.y = pkbf2(wv[kp * 2 + 9], wv[kp * 2 + 8]);
            o.z = pkbf2(rv[kp * 2 + 1], rv[kp * 2]);
            o.w = pkbf2(rv[kp * 2 + 9], rv[kp * 2 + 8]);
            g_wgf[(li * 16 + nt) * 32 + lane] = o;
        }
    } else if (idx < 9 * 8 * 128 + 6 * 128 + KC0 * 56) {
        int id3 = idx - (9 * 8 * 128 + 6 * 128);
        int kc = id3 / 56;
        int n = id3 - kc * 56;
        float wv[16], rv[16];
#pragma unroll
        for (int kk = 0; kk < 16; kk++) {
            int k = kc * 16 + kk;
            float v = (k < 1433) ? w_feat[k * 56 + n] : 0.f;
            wv[kk] = v;
            rv[kk] = bfres(v);
        }
        int nt = n >> 3;
#pragma unroll
        for (int kp = 0; kp < 4; kp++) {
            int lane = (n & 7) * 4 + kp;
            uint4 o;
            o.x = pkbf2(wv[kp * 2 + 1], wv[kp * 2]);
            o.y = pkbf2(wv[kp * 2 + 9], wv[kp * 2 + 8]);
            o.z = pkbf2(rv[kp * 2 + 1], rv[kp * 2]);
            o.w = pkbf2(rv[kp * 2 + 9], rv[kp * 2 + 8]);
            g_wff[(kc * 7 + nt) * 32 + lane] = o;
        }
    } else if (idx < 9 * 8 * 128 + 6 * 128 + KC0 * 56 + NC) {
        int j = idx - (9 * 8 * 128 + 6 * 128 + KC0 * 56);
        float fb = out_b[j];
        float fw[16];
#pragma unroll
        for (int k = 0; k < 16; k++) fw[k] = 0.f;
        for (int t = 0; t < 56; t++) {
            float wv = out_w[t * NC + j];
            fb += mas_b2[t] * wv;
#pragma unroll
            for (int k = 0; k < 16; k++) fw[k] += masW2[k * 56 + t] * wv;
        }
#pragma unroll
        for (int k = 0; k < 16; k++) g_fw[k * NC + j] = fw[k];
        g_fb[j] = fb;
    }
}

// ---------------- prep: mas-fused GCN weights -> frags + bvec (both blocks) -----
__global__ void k_prep(const float* __restrict__ mas_w, const float* __restrict__ mas_b,
                       const float* __restrict__ gcn0_w) {
    int b = blockIdx.x;                    // 0 -> m=1, 1 -> m=2
    const float* masW = mas_w + b * PH * D0;
    const float* mb_p = mas_b + b * D0;
    const float* Wg = gcn0_w + (b + 1) * D0 * DH;
    int li = (b + 1) * NL;
    __shared__ float mw[16 * 56];
    __shared__ float mb[56];
    int j = threadIdx.x;
    for (int i = j; i < 16 * 56; i += 128) mw[i] = masW[i];
    if (j < 56) mb[j] = mb_p[j];
    __syncthreads();
    float accw[16], rw[16];
#pragma unroll
    for (int k = 0; k < 16; k++) accw[k] = 0.f;
    float accb = 0.f;
    for (int t = 0; t < 56; t++) {
        float wv = Wg[t * 128 + j];
        accb += mb[t] * wv;
#pragma unroll
        for (int k = 0; k < 16; k++) accw[k] += mw[k * 56 + t] * wv;
    }
#pragma unroll
    for (int k = 0; k < 16; k++) rw[k] = bfres(accw[k]);
    int nt = j >> 3;
#pragma unroll
    for (int kp = 0; kp < 4; kp++) {
        int lane = (j & 7) * 4 + kp;
        uint4 o;
        o.x = pkbf2(accw[kp * 2 + 1], accw[kp * 2]);
        o.y = pkbf2(accw[kp * 2 + 9], accw[kp * 2 + 8]);
        o.z = pkbf2(rw[kp * 2 + 1], rw[kp * 2]);
        o.w = pkbf2(rw[kp * 2 + 9], rw[kp * 2 + 8]);
        g_wgf[(li * 16 + nt) * 32 + lane] = o;
    }
    g_bvec[b * DH + j] = accb;
}

// ---------------- 56-dim aggregation (warp/dst, unroll 2) ----------------
__global__ void k_agg56(const float* __restrict__ in, float* __restrict__ out,
                        const float* __restrict__ bias, int do_relu) {
    int w = (blockIdx.x * blockDim.x + threadIdx.x) >> 5;
    int lane = threadIdx.x & 31;
    if (w >= NPAD) return;
    int c1 = lane + 32;
    float a0 = 0.f, a1 = 0.f;
    if (w < NN) {
        int e0 = g_off[w], e1 = g_off[w + 1];
        int e = e0;
        for (; e + 2 <= e1; e += 2) {
            int s0 = g_srcs[e], s1 = g_srcs[e + 1];
            float m0 = g_norm[e], m1 = g_norm[e + 1];
            const float* r0 = in + s0 * 56;
            const float* r1 = in + s1 * 56;
            a0 += m0 * r0[lane] + m1 * r1[lane];
            if (c1 < 56) a1 += m0 * r0[c1] + m1 * r1[c1];
        }
        if (e < e1) {
            int s0 = g_srcs[e];
            float m0 = g_norm[e];
            const float* r0 = in + s0 * 56;
            a0 += m0 * r0[lane];
            if (c1 < 56) a1 += m0 * r0[c1];
        }
    }
    float b0 = bias ? bias[lane] : 0.f;
    float v0 = a0 + b0;
    if (do_relu) v0 = fmaxf(v0, 0.f);
    out[w * 56 + lane] = v0;
    if (c1 < 56) {
        float b1 = bias ? bias[c1] : 0.f;
        float v1 = a1 + b1;
        if (do_relu) v1 = fmaxf(v1, 0.f);
        out[w * 56 + c1] = v1;
    }
}

// ---------------- tensor-core fused AGG16 + GCN(16->128) + GAT(128->128) --------
#define HS 136  // smem row stride (bf16), conflict-free for ldmatrix
__global__ __launch_bounds__(256)
void k_fused_mma(const float* __restrict__ hin,
                 const uint4* __restrict__ wgf, const float* __restrict__ bg,
                 const float* __restrict__ bvec,
                 const uint4* __restrict__ wtf,
                 const float* __restrict__ asrc, const float* __restrict__ adst) {
    __shared__ __align__(16) float sAgg[64 * 16];
    __shared__ __align__(16) __nv_bfloat16 sHh[64 * HS];
    __shared__ __align__(16) __nv_bfloat16 sHl[64 * HS];
    int tid = threadIdx.x;
    int lane = tid & 31;
    int wid = tid >> 5;
    int n0 = blockIdx.x * 64;

    // ---- agg phase: dst = n0 + wid*8 + quad, channels c4..c4+3 ----
    {
        int dl = wid * 8 + (lane >> 2);
        int d = n0 + dl;
        int c4 = (lane & 3) * 4;
        float4 a = make_float4(0.f, 0.f, 0.f, 0.f);
        if (d < NN) {
            int e0 = g_off[d], e1 = g_off[d + 1];
            for (int e = e0; e < e1; e += 2) {
                int i1 = (e + 1 < e1) ? e + 1 : e;
                int s0 = g_srcs[e], s1 = g_srcs[i1];
                float m0 = g_norm[e];
                float m1 = (e + 1 < e1) ? g_norm[i1] : 0.f;
                float4 h0 = *(const float4*)(hin + s0 * 16 + c4);
                float4 h1 = *(const float4*)(hin + s1 * 16 + c4);
                a.x += m0 * h0.x + m1 * h1.x;
                a.y += m0 * h0.y + m1 * h1.y;
                a.z += m0 * h0.z + m1 * h1.z;
                a.w += m0 * h0.w + m1 * h1.w;
            }
        }
        *(float4*)&sAgg[dl * 16 + c4] = a;
    }
    __syncthreads();

    int warp_m = wid & 3;
    int warp_n = wid >> 2;
    int rl = warp_m * 16 + (lane >> 2);
    int r = n0 + rl;
    int kq = (lane & 3) * 2;

    // GEMM1 A fragments from smem agg [64][16]
    const float* ap = sAgg + rl * 16;
    float2 a00 = *(const float2*)(ap + kq);
    float2 a10 = *(const float2*)(ap + 8 * 16 + kq);
    float2 a02 = *(const float2*)(ap + kq + 8);
    float2 a12 = *(const float2*)(ap + 8 * 16 + kq + 8);
    uint32_t ah[4], al[4];
    ah[0] = pkbf2(a00.y, a00.x); al[0] = pkbf2(bfres(a00.y), bfres(a00.x));
    ah[1] = pkbf2(a10.y, a10.x); al[1] = pkbf2(bfres(a10.y), bfres(a10.x));
    ah[2] = pkbf2(a02.y, a02.x); al[2] = pkbf2(bfres(a02.y), bfres(a02.x));
    ah[3] = pkbf2(a12.y, a12.x); al[3] = pkbf2(bfres(a12.y), bfres(a12.x));

    float acc[8][4];
#pragma unroll
    for (int t = 0; t < 8; t++)
        acc[t][0] = acc[t][1] = acc[t][2] = acc[t][3] = 0.f;
#pragma unroll
    for (int t = 0; t < 8; t++) {
        uint4 b = wgf[(warp_n * 8 + t) * 32 + lane];
        mma16816(acc[t], ah, b.x, b.y);
        mma16816(acc[t], ah, b.z, b.w);
        mma16816(acc[t], al, b.x, b.y);
    }

    // epilogue 1: bias (+nsum correction) + relu -> smem split-bf16
    float ns0 = 0.f, ns1 = 0.f;
    if (bvec) { ns0 = g_nsum[r]; ns1 = g_nsum[r + 8]; }
#pragma unroll
    for (int t = 0; t < 8; t++) {
        int c = warp_n * 64 + t * 8 + kq;
        float b0 = bg[c], b1 = bg[c + 1];
        float v0 = acc[t][0] + b0, v1 = acc[t][1] + b1;
        float v2 = acc[t][2] + b0, v3 = acc[t][3] + b1;
        if (bvec) {
            float bv0 = bvec[c], bv1 = bvec[c + 1];
            v0 += ns0 * bv0; v1 += ns0 * bv1;
            v2 += ns1 * bv0; v3 += ns1 * bv1;
        }
        v0 = fmaxf(v0, 0.f); v1 = fmaxf(v1, 0.f);
        v2 = fmaxf(v2, 0.f); v3 = fmaxf(v3, 0.f);
        int ro = rl * HS + c;
        *(uint32_t*)&sHh[ro] = pkbf2(v1, v0);
        *(uint32_t*)&sHl[ro] = pkbf2(bfres(v1), bfres(v0));
        *(uint32_t*)&sHh[ro + 8 * HS] = pkbf2(v3, v2);
        *(uint32_t*)&sHl[ro + 8 * HS] = pkbf2(bfres(v3), bfres(v2));
    }
    __syncthreads();

    // GEMM2: hh = h @ Wt
#pragma unroll
    for (int t = 0; t < 8; t++)
        acc[t][0] = acc[t][1] = acc[t][2] = acc[t][3] = 0.f;
    uint32_t baseHh = (uint32_t)__cvta_generic_to_shared(sHh);
    uint32_t baseHl = (uint32_t)__cvta_generic_to_shared(sHl);
    int arow = warp_m * 16 + (lane & 15);
#pragma unroll
    for (int kc = 0; kc < 8; kc++) {
        int acol = kc * 16 + (lane >> 4) * 8;
        uint32_t off = (arow * HS + acol) * 2;
        uint32_t a2h[4], a2l[4];
        ldm_x4(a2h[0], a2h[1], a2h[2], a2h[3], baseHh + off);
        ldm_x4(a2l[0], a2l[1], a2l[2], a2l[3], baseHl + off);
        const uint4* wp = wtf + kc * 16 * 32;
#pragma unroll
        for (int t = 0; t < 8; t++) {
            uint4 b = wp[(warp_n * 8 + t) * 32 + lane];
            mma16816(acc[t], a2h, b.x, b.y);
            mma16816(acc[t], a2h, b.z, b.w);
            mma16816(acc[t], a2l, b.x, b.y);
        }
    }

    // epilogue 2: store hh + exp'd es pair + ed for this warp's 4 heads
    float* row0p = g_x2 + r * 128;
    float* row1p = g_x2 + (r + 8) * 128;
#pragma unroll
    for (int h2 = 0; h2 < 4; h2++) {
        int head = warp_n * 4 + h2;
        float vs0 = 0.f, vs1 = 0.f, vd0 = 0.f, vd1 = 0.f;
#pragma unroll
        for (int q = 0; q < 2; q++) {
            int t = 2 * h2 + q;
            int c = warp_n * 64 + t * 8 + kq;
            float av0 = asrc[c], av1 = asrc[c + 1];
            float dv0 = adst[c], dv1 = adst[c + 1];
            float c0 = acc[t][0], c1 = acc[t][1], c2 = acc[t][2], c3 = acc[t][3];
            *(float2*)(row0p + c) = make_float2(c0, c1);
            *(float2*)(row1p + c) = make_float2(c2, c3);
            vs0 += c0 * av0 + c1 * av1;
            vs1 += c2 * av0 + c3 * av1;
            vd0 += c0 * dv0 + c1 * dv1;
            vd1 += c2 * dv0 + c3 * dv1;
        }
        vs0 += __shfl_xor_sync(0xffffffffu, vs0, 1);
        vs0 += __shfl_xor_sync(0xffffffffu, vs0, 2);
        vs1 += __shfl_xor_sync(0xffffffffu, vs1, 1);
        vs1 += __shfl_xor_sync(0xffffffffu, vs1, 2);
        vd0 += __shfl_xor_sync(0xffffffffu, vd0, 1);
        vd0 += __shfl_xor_sync(0xffffffffu, vd0, 2);
        vd1 += __shfl_xor_sync(0xffffffffu, vd1, 1);
        vd1 += __shfl_xor_sync(0xffffffffu, vd1, 2);
        if ((lane & 3) == 0) {
            g_esx[r * NH + head] = make_float2(__expf(vs0), __expf(0.2f * vs0));
            g_esx[(r + 8) * NH + head] = make_float2(__expf(vs1), __expf(0.2f * vs1));
            g_ed[r * NH + head] = vd0;
            g_ed[(r + 8) * NH + head] = vd1;
        }
    }
}

// ---------------- scalar fused GCN(56->128)+GAT (layer 0,0 only) ----------------
#define HT_STRIDE 36
__global__ void k_fused56(const float* __restrict__ agg,
                          const float* __restrict__ Wg, const float* __restrict__ bg,
                          const float* __restrict__ Wt,
                          const float* __restrict__ asrc, const float* __restrict__ adst) {
    __shared__ __align__(16) float as_t[D0 * 32];
    __shared__ __align__(16) float h_t[DH * HT_STRIDE];
    int j = threadIdx.x;
    int n0 = blockIdx.x * 32;
    for (int i = j; i < 32 * D0; i += 128) {
        int r = i / D0, k = i - r * D0;
        as_t[k * 32 + r] = agg[(n0 + r) * D0 + k];
    }
    __syncthreads();

    unsigned long long acc2[16];
#pragma unroll
    for (int p = 0; p < 16; p++) acc2[p] = 0ull;
#pragma unroll 2
    for (int k = 0; k < D0; k++) {
        const ulonglong2* hp = reinterpret_cast<const ulonglong2*>(&as_t[k * 32]);
        unsigned long long w2;
        PACKW(w2, Wg[k * 128 + j]);
        ulonglong2 v0 = hp[0], v1 = hp[1], v2 = hp[2], v3 = hp[3];
        FFMA2(acc2[0], v0.x, w2); FFMA2(acc2[1], v0.y, w2);
        FFMA2(acc2[2], v1.x, w2); FFMA2(acc2[3], v1.y, w2);
        FFMA2(acc2[4], v2.x, w2); FFMA2(acc2[5], v2.y, w2);
        FFMA2(acc2[6], v3.x, w2); FFMA2(acc2[7], v3.y, w2);
        ulonglong2 v4 = hp[4], v5 = hp[5], v6 = hp[6], v7 = hp[7];
        FFMA2(acc2[8],  v4.x, w2); FFMA2(acc2[9],  v4.y, w2);
        FFMA2(acc2[10], v5.x, w2); FFMA2(acc2[11], v5.y, w2);
        FFMA2(acc2[12], v6.x, w2); FFMA2(acc2[13], v6.y, w2);
        FFMA2(acc2[14], v7.x, w2); FFMA2(acc2[15], v7.y, w2);
    }
    {
        float bb = bg[j];
#pragma unroll
        for (int p = 0; p < 16; p++) {
            float lo, hi;
            UNPK(lo, hi, acc2[p]);
            int rr = 2 * p;
            h_t[j * HT_STRIDE + rr]     = fmaxf(lo + bb, 0.f);
            h_t[j * HT_STRIDE + rr + 1] = fmaxf(hi + bb, 0.f);
        }
    }
    __syncthreads();

#pragma unroll
    for (int p = 0; p < 16; p++) acc2[p] = 0ull;
#pragma unroll 2
    for (int k = 0; k < DH; k++) {
        const ulonglong2* hp = reinterpret_cast<const ulonglong2*>(&h_t[k * HT_STRIDE]);
        unsigned long long w2;
        PACKW(w2, Wt[k * 128 + j]);
        ulonglong2 v0 = hp[0], v1 = hp[1], v2 = hp[2], v3 = hp[3];
        FFMA2(acc2[0], v0.x, w2); FFMA2(acc2[1], v0.y, w2);
        FFMA2(acc2[2], v1.x, w2); FFMA2(acc2[3], v1.y, w2);
        FFMA2(acc2[4], v2.x, w2); FFMA2(acc2[5], v2.y, w2);
        FFMA2(acc2[6], v3.x, w2); FFMA2(acc2[7], v3.y, w2);
        ulonglong2 v4 = hp[4], v5 = hp[5], v6 = hp[6], v7 = hp[7];
        FFMA2(acc2[8],  v4.x, w2); FFMA2(acc2[9],  v4.y, w2);
        FFMA2(acc2[10], v5.x, w2); FFMA2(acc2[11], v5.y, w2);
        FFMA2(acc2[12], v6.x, w2); FFMA2(acc2[13], v6.y, w2);
        FFMA2(acc2[14], v7.x, w2); FFMA2(acc2[15], v7.y, w2);
    }
    float av = asrc[j], dv = adst[j];
    int head = j >> 4;
#pragma unroll
    for (int p = 0; p < 16; p++) {
        float lo, hi;
        UNPK(lo, hi, acc2[p]);
#pragma unroll
        for (int q = 0; q < 2; q++) {
            float h = q ? hi : lo;
            int rr = n0 + 2 * p + q;
            g_x2[rr * 128 + j] = h;
            float vs = h * av;
            float vd = h * dv;
#pragma unroll
            for (int off = 8; off > 0; off >>= 1) {
                vs += __shfl_xor_sync(0xffffffffu, vs, off);
                vd += __shfl_xor_sync(0xffffffffu, vd, off);
            }
            if ((j & 15) == 0) {
                g_esx[rr * NH + head] = make_float2(__expf(vs), __expf(0.2f * vs));
                g_ed[rr * NH + head] = vd;
            }
        }
    }
}

// ---------------- single-pass GAT edge aggregation (factored exp) ----------------
// w_edge = exp(leaky(es+ed)) = (es+ed>0) ? exp(es)exp(ed) : exp(.2es)exp(.2ed);
// es+ed>0  <=>  exp(es) > exp(-ed). Zero per-edge MUFU.
__global__ void k_gat_edge(const float* __restrict__ gb) {
    int w = (blockIdx.x * blockDim.x + threadIdx.x) >> 5;
    int lane = threadIdx.x & 31;
    if (w >= NN) return;
    int h8 = lane & 7;        // head this lane computes weight for
    int eg = lane >> 3;       // edge slot 0..3
    int hsel = lane >> 2;     // head owning this lane's 4 gather channels
    float edh = g_ed[w * NH + h8];
    float E1 = __expf(edh);
    float E2 = __expf(0.2f * edh);
    float T  = __expf(-edh);
    int e0 = g_off[w], e1 = g_off[w + 1];
    unsigned long long acc01 = 0ull, acc23 = 0ull;
    float dsum = 0.f;
    for (int e = e0; e < e1; e += 4) {
        int ee = e + eg;
        int idx = ee < e1 ? ee : e1 - 1;
        int soff = g_srcs[idx] << 7;   // row offset in floats (src * 128)
        float2 p = g_esx[(soff >> 4) + h8];   // src*8 = soff/16
        float wv = (p.x > T) ? p.x * E1 : p.y * E2;
        wv = (ee < e1) ? wv : 0.f;
        dsum += wv;
#pragma unroll
        for (int q = 0; q < 4; q++) {
            float wb = __shfl_sync(0xffffffffu, wv, q * 8 + hsel);
            int so = __shfl_sync(0xffffffffu, soff, q * 8);
            unsigned long long wb2;
            PACKW(wb2, wb);
            ulonglong2 hv = reinterpret_cast<const ulonglong2*>(g_x2 + so)[lane];
            FFMA2(acc01, hv.x, wb2);
            FFMA2(acc23, hv.y, wb2);
        }
    }
    dsum += __shfl_xor_sync(0xffffffffu, dsum, 8);
    dsum += __shfl_xor_sync(0xffffffffu, dsum, 16);
    float db = __shfl_sync(0xffffffffu, dsum, hsel);
    float inv = 1.f / db;
    float4 acc;
    UNPK(acc.x, acc.y, acc01);
    UNPK(acc.z, acc.w, acc23);
    acc.x *= inv; acc.y *= inv; acc.z *= inv; acc.w *= inv;
#pragma unroll
    for (int off = 4; off <= 16; off <<= 1) {
        acc.x += __shfl_xor_sync(0xffffffffu, acc.x, off);
        acc.y += __shfl_xor_sync(0xffffffffu, acc.y, off);
        acc.z += __shfl_xor_sync(0xffffffffu, acc.z, off);
        acc.w += __shfl_xor_sync(0xffffffffu, acc.w, off);
    }
    if (lane < 4) {
        float4 gb4 = reinterpret_cast<const float4*>(gb)[lane];
        float4 r;
        r.x = acc.x * 0.125f + gb4.x;
        r.y = acc.y * 0.125f + gb4.y;
        r.z = acc.z * 0.125f + gb4.z;
        r.w = acc.w * 0.125f + gb4.w;
        reinterpret_cast<float4*>(g_hA + w * PH)[lane] = r;
    }
}

// ---------------- fused MAS+output ----------------
__global__ void k_masout(float* __restrict__ out) {
    int t = blockIdx.x * blockDim.x + threadIdx.x;
    if (t >= NN * NC) return;
    int n = t / NC, c = t - n * NC;
    float acc = g_fb[c];
    const float* hr = g_hA + n * PH;
#pragma unroll
    for (int k = 0; k < 16; k++) acc += hr[k] * g_fw[k * NC + c];
    out[t] = acc;
}

// ---------------- launcher ----------------
extern "C" void kernel_launch(void* const* d_in, const int* in_sizes, int n_in,
                              void* d_out, int out_size) {
    const float* x      = (const float*)d_in[0];
    const int*   ei     = (const int*)d_in[1];
    const float* w_feat = (const float*)d_in[2];
    const float* b_feat = (const float*)d_in[3];
    const float* gcn0_w = (const float*)d_in[4];
    const float* gcn0_b = (const float*)d_in[5];
    const float* gcn_w  = (const float*)d_in[6];
    const float* gcn_b  = (const float*)d_in[7];
    const float* gat_w  = (const float*)d_in[8];
    const float* gat_as = (const float*)d_in[9];
    const float* gat_ad = (const float*)d_in[10];
    const float* gat_b  = (const float*)d_in[11];
    const float* mas_w  = (const float*)d_in[12];
    const float* mas_b  = (const float*)d_in[13];
    const float* out_w  = (const float*)d_in[14];
    const float* out_b  = (const float*)d_in[15];
    float* out = (float*)d_out;
    (void)in_sizes; (void)n_in; (void)out_size;

    float *p_x1, *p_hA, *p_hB, *p_agg, *p_bvec;
    uint4 *p_wtf, *p_wgf;
    cudaGetSymbolAddress((void**)&p_x1, g_x1);
    cudaGetSymbolAddress((void**)&p_hA, g_hA);
    cudaGetSymbolAddress((void**)&p_hB, g_hB);
    cudaGetSymbolAddress((void**)&p_agg, g_agg);
    cudaGetSymbolAddress((void**)&p_bvec, g_bvec);
    cudaGetSymbolAddress((void**)&p_wtf, g_wtf);
    cudaGetSymbolAddress((void**)&p_wgf, g_wgf);

    // CSR build; k_swz + k_prep before gemm0; gemm0 at capture slot #4
    k_deg_init<<<(NPAD + 255) / 256, 256>>>();
    k_deg_count<<<(EE + 255) / 256, 256>>>(ei);
    k_swz<<<(9 * 8 * 128 + 6 * 128 + KC0 * 56 + NC + 255) / 256, 256>>>(
        gat_w, gcn_w, w_feat, mas_w + 2 * PH * D0, mas_b + 2 * D0, out_w, out_b);
    k_gemm0<<<(NN + 127) / 128, 256>>>(x);
    k_prep<<<2, 128>>>(mas_w, mas_b, gcn0_w);
    k_scan1<<<NB_SCAN, 256>>>();
    k_scan2<<<1, 256>>>();
    k_scan3<<<NB_SCAN, 256>>>();
    k_fill<<<(ENT + 255) / 256, 256>>>(ei);

    // GNFE: aggregate transformed features (+bias, relu)
    k_agg56<<<NPAD / 8, 256>>>(p_x1, p_hB, b_feat, 1);

    for (int m = 0; m < NL; m++) {
        for (int i = 0; i < NL; i++) {
            int li = m * NL + i;
            const float* as = gat_as + li * NH * PH;
            const float* ad = gat_ad + li * NH * PH;
            const uint4* wtf = p_wtf + li * 8 * 16 * 32;
            if (i == 0 && m == 0) {
                k_agg56<<<NPAD / 8, 256>>>(p_hB, p_agg, (const float*)0, 0);
                k_fused56<<<NPAD / 32, 128>>>(p_agg, gcn0_w, gcn0_b,
                                              gat_w + li * DH * DH, as, ad);
            } else if (i == 0) {
                k_fused_mma<<<NPAD / 64, 256>>>(p_hA, p_wgf + li * 16 * 32,
                                                gcn0_b + m * DH,
                                                p_bvec + (m - 1) * DH, wtf, as, ad);
            } else {
                k_fused_mma<<<NPAD / 64, 256>>>(
                    p_hA, p_wgf + li * 16 * 32,
                    gcn_b + (m * (NL - 1) + (i - 1)) * DH,
                    (const float*)0, wtf, as, ad);
            }
            k_gat_edge<<<(NN * 32 + 255) / 256, 256>>>(gat_b + li * PH);
        }
    }
    k_masout<<<(NN * NC + 255) / 256, 256>>>(out);
}

// round 16
// speedup vs baseline: 1.0858x; 1.0858x over previous
#include <cuda_runtime.h>
#include <cuda_bf16.h>
#include <math.h>
#include <stdint.h>

#define NN 50000
#define NPAD 50048
#define EE 800000
#define ENT (EE + NN)
#define NH 8
#define PH 16
#define DH 128
#define D0 56
#define NC 7
#define NL 3
#define NB_SCAN 196  // ceil(50000/256)
#define KC0 90       // ceil(1433/16) k-chunks for gemm0

// packed fp32x2 FMA (sm_103a)
#define FFMA2(acc, h, w) \
    asm("fma.rn.f32x2 %0, %1, %2, %0;" : "+l"(acc) : "l"(h), "l"(w))
#define PACKW(dst, f) \
    asm("mov.b64 %0, {%1, %1};" : "=l"(dst) : "r"(__float_as_uint(f)))
#define UNPK(lo, hi, v) \
    do { unsigned int _a, _b; \
         asm("mov.b64 {%0,%1}, %2;" : "=r"(_a), "=r"(_b) : "l"(v)); \
         lo = __uint_as_float(_a); hi = __uint_as_float(_b); } while (0)

__device__ __forceinline__ uint32_t pkbf2(float hi, float lo) {
    uint32_t d;
    asm("cvt.rn.bf16x2.f32 %0, %1, %2;" : "=r"(d) : "f"(hi), "f"(lo));
    return d;
}
__device__ __forceinline__ float bfres(float v) {
    return v - __bfloat162float(__float2bfloat16(v));
}
__device__ __forceinline__ void mma16816(float* c, const uint32_t* a,
                                         uint32_t b0, uint32_t b1) {
    asm volatile(
        "mma.sync.aligned.m16n8k16.row.col.f32.bf16.bf16.f32 "
        "{%0,%1,%2,%3}, {%4,%5,%6,%7}, {%8,%9}, {%0,%1,%2,%3};"
        : "+f"(c[0]), "+f"(c[1]), "+f"(c[2]), "+f"(c[3])
        : "r"(a[0]), "r"(a[1]), "r"(a[2]), "r"(a[3]), "r"(b0), "r"(b1));
}
__device__ __forceinline__ void ldm_x4(uint32_t& r0, uint32_t& r1, uint32_t& r2,
                                       uint32_t& r3, uint32_t addr) {
    asm volatile("ldmatrix.sync.aligned.m8n8.x4.shared.b16 {%0,%1,%2,%3}, [%4];"
                 : "=r"(r0), "=r"(r1), "=r"(r2), "=r"(r3) : "r"(addr));
}

// ---------------- scratch ----------------
__device__ int   g_deg[NN];
__device__ int   g_off[NN + 1];
__device__ int   g_cur[NN];
__device__ int   g_part[256];
__device__ int   g_partoff[256];
__device__ int   g_srcs[ENT + 8];
__device__ float g_norm[ENT + 8];
__device__ float g_dinv[NN];
__device__ float g_nsum[NPAD];
__device__ float g_hB[NPAD * D0];
__device__ float g_hA[NPAD * PH];
__device__ float g_x1[NPAD * D0];
__device__ float g_x2[NPAD * DH];
__device__ float g_es[NPAD * NH];
__device__ float g_ed[NPAD * NH];
__device__ float g_bvec[2 * DH];
__device__ float g_fw[PH * NC];
__device__ float g_fb[NC];
__device__ uint4 g_wtf[9 * 8 * 16 * 32];  // GAT W frags: [li][kc][nt][lane]
__device__ uint4 g_wgf[9 * 16 * 32];      // GCN W frags (k=16): [li][nt][lane]
__device__ uint4 g_wff[KC0 * 7 * 32];     // w_feat frags: [kc][nt][lane]
__device__ uint4 g_wg56[4 * 16 * 32];     // gcn0_w[0] frags (56->64 pad): [kc][nt][lane]

// ---------------- CSR construction ----------------
__global__ void k_deg_count(const int* __restrict__ ei) {
    int e = blockIdx.x * blockDim.x + threadIdx.x;
    if (e < EE) atomicAdd(&g_deg[ei[EE + e]], 1);
}

__global__ void k_scan1() {
    __shared__ int sh[256];
    int t = threadIdx.x;
    int i = blockIdx.x * 256 + t;
    int d = (i < NN) ? g_deg[i] + 1 : 0;   // +1 self-loop
    sh[t] = d;
    __syncthreads();
#pragma unroll
    for (int off = 1; off < 256; off <<= 1) {
        int v = (t >= off) ? sh[t - off] : 0;
        __syncthreads();
        sh[t] += v;
        __syncthreads();
    }
    if (t == 255) g_part[blockIdx.x] = sh[255];
    if (i < NN) g_off[i] = sh[t] - d;
}

__global__ void k_scan2() {
    __shared__ int sh[256];
    int t = threadIdx.x;
    int v = (t < NB_SCAN) ? g_part[t] : 0;
    sh[t] = v;
    __syncthreads();
#pragma unroll
    for (int off = 1; off < 256; off <<= 1) {
        int u = (t >= off) ? sh[t - off] : 0;
        __syncthreads();
        sh[t] += u;
        __syncthreads();
    }
    g_partoff[t] = sh[t] - v;
}

__global__ void k_scan3() {
    int i = blockIdx.x * blockDim.x + threadIdx.x;
    if (i >= NN) return;
    int off = g_off[i] + g_partoff[i >> 8];
    g_off[i] = off;
    g_cur[i] = off;
    g_dinv[i] = rsqrtf((float)(g_deg[i] + 1));
    g_deg[i] = 0;        // reset for next replay (graph capture)
    g_nsum[i] = 0.f;     // reset for k_fill atomics
    if (i == 0) g_off[NN] = ENT;
}

__global__ void k_fill(const int* __restrict__ ei) {
    int e = blockIdx.x * blockDim.x + threadIdx.x;
    if (e >= ENT) return;
    int s, d;
    if (e < EE) { s = ei[e]; d = ei[EE + e]; }
    else        { s = d = e - EE; }
    int p = atomicAdd(&g_cur[d], 1);
    float nm = g_dinv[s] * g_dinv[d];
    g_srcs[p] = s;
    g_norm[p] = nm;
    atomicAdd(&g_nsum[d], nm);
}

// ---------------- smem-free tensor-core GEMM0 (R11 proven version) -------------
__device__ __forceinline__ void g0_load(const float* xp1, const float* xp2,
                                        bool p1, bool p2, int kb, float* v) {
    v[0] = p1 ? xp1[kb]     : 0.f;
    v[1] = p1 ? xp1[kb + 1] : 0.f;
    v[2] = p1 ? xp1[kb + 8] : 0.f;
    v[3] = p1 ? xp1[kb + 9] : 0.f;
    v[4] = p2 ? xp2[kb]     : 0.f;
    v[5] = p2 ? xp2[kb + 1] : 0.f;
    v[6] = p2 ? xp2[kb + 8] : 0.f;
    v[7] = p2 ? xp2[kb + 9] : 0.f;
}
__device__ __forceinline__ void g0_mma(const float* v, const uint4* wp,
                                       float acc[7][4]) {
    uint32_t ah[4], al[4];
    ah[0] = pkbf2(v[1], v[0]); al[0] = pkbf2(bfres(v[1]), bfres(v[0]));
    ah[1] = pkbf2(v[5], v[4]); al[1] = pkbf2(bfres(v[5]), bfres(v[4]));
    ah[2] = pkbf2(v[3], v[2]); al[2] = pkbf2(bfres(v[3]), bfres(v[2]));
    ah[3] = pkbf2(v[7], v[6]); al[3] = pkbf2(bfres(v[7]), bfres(v[6]));
#pragma unroll
    for (int nt = 0; nt < 7; nt++) {
        uint4 b = wp[nt * 32];
        mma16816(acc[nt], ah, b.x, b.y);
        mma16816(acc[nt], ah, b.z, b.w);
        mma16816(acc[nt], al, b.x, b.y);
    }
}

__global__ __launch_bounds__(256)
void k_gemm0(const float* __restrict__ x) {
    int tid = threadIdx.x;
    int lane = tid & 31;
    int wid = tid >> 5;
    int row0 = blockIdx.x * 128;
    int r1 = row0 + wid * 16 + (lane >> 2);
    int r2 = r1 + 8;
    int kq = (lane & 3) * 2;
    bool p1 = r1 < NN, p2 = r2 < NN;
    const float* xp1 = x + (int64_t)r1 * 1433 + kq;
    const float* xp2 = x + (int64_t)r2 * 1433 + kq;

    float acc[7][4];
#pragma unroll
    for (int nt = 0; nt < 7; nt++)
        acc[nt][0] = acc[nt][1] = acc[nt][2] = acc[nt][3] = 0.f;

    const uint4* wbase = g_wff + lane;

    int kc = 0;
    for (; kc + 2 <= KC0 - 1; kc += 2) {
        float va[8], vb[8];
        g0_load(xp1, xp2, p1, p2, kc * 16, va);
        g0_load(xp1, xp2, p1, p2, kc * 16 + 16, vb);
        g0_mma(va, wbase + kc * 7 * 32, acc);
        g0_mma(vb, wbase + (kc + 1) * 7 * 32, acc);
    }
    {
        float va[8];
        g0_load(xp1, xp2, p1, p2, kc * 16, va);
        g0_mma(va, wbase + kc * 7 * 32, acc);
    }
    {
        const int kb = (KC0 - 1) * 16;
        float v[8];
        v[0] = p1 ? xp1[kb]     : 0.f;
        v[1] = p1 ? xp1[kb + 1] : 0.f;
        v[2] = (p1 && kq == 0) ? xp1[kb + 8] : 0.f;
        v[3] = 0.f;
        v[4] = p2 ? xp2[kb]     : 0.f;
        v[5] = p2 ? xp2[kb + 1] : 0.f;
        v[6] = (p2 && kq == 0) ? xp2[kb + 8] : 0.f;
        v[7] = 0.f;
        g0_mma(v, wbase + (KC0 - 1) * 7 * 32, acc);
    }

#pragma unroll
    for (int nt = 0; nt < 7; nt++) {
        int col = nt * 8 + kq;
        if (p1) *(float2*)&g_x1[r1 * 56 + col] = make_float2(acc[nt][0], acc[nt][1]);
        if (p2) *(float2*)&g_x1[r2 * 56 + col] = make_float2(acc[nt][2], acc[nt][3]);
    }
}

// ---------------- weight fragment swizzles (+ w_feat, gcn0_w[0], out prep) ------
__global__ void k_swz(const float* __restrict__ gat_w, const float* __restrict__ gcn_w,
                      const float* __restrict__ w_feat, const float* __restrict__ gcn0_w,
                      const float* __restrict__ masW2, const float* __restrict__ mas_b2,
                      const float* __restrict__ out_w, const float* __restrict__ out_b) {
    int idx = blockIdx.x * blockDim.x + threadIdx.x;
    if (idx < 9 * 8 * 128) {
        int li = idx >> 10;
        int rem = idx & 1023;
        int kc = rem >> 7;
        int n = rem & 127;
        const float* W = gat_w + li * 128 * 128;
        float wv[16], rv[16];
#pragma unroll
        for (int kk = 0; kk < 16; kk++) {
            float v = W[(kc * 16 + kk) * 128 + n];
            wv[kk] = v;
            rv[kk] = bfres(v);
        }
        int nt = n >> 3;
#pragma unroll
        for (int kp = 0; kp < 4; kp++) {
            int lane = (n & 7) * 4 + kp;
            uint4 o;
            o.x = pkbf2(wv[kp * 2 + 1], wv[kp * 2]);
            o.y = pkbf2(wv[kp * 2 + 9], wv[kp * 2 + 8]);
            o.z = pkbf2(rv[kp * 2 + 1], rv[kp * 2]);
            o.w = pkbf2(rv[kp * 2 + 9], rv[kp * 2 + 8]);
            g_wtf[((li * 8 + kc) * 16 + nt) * 32 + lane] = o;
        }
    } else if (idx < 9 * 8 * 128 + 6 * 128) {
        int id2 = idx - 9 * 8 * 128;
        int j = id2 >> 7;          // 0..5
        int n = id2 & 127;
        int m = j >> 1, i = 1 + (j & 1);
        int li = m * 3 + i;
        const float* W = gcn_w + (m * 2 + (i - 1)) * 16 * 128;
        float wv[16], rv[16];
#pragma unroll
        for (int kk = 0; kk < 16; kk++) {
            float v = W[kk * 128 + n];
            wv[kk] = v;
            rv[kk] = bfres(v);
        }
        int nt = n >> 3;
#pragma unroll
        for (int kp = 0; kp < 4; kp++) {
            int lane = (n & 7) * 4 + kp;
            uint4 o;
            o.x = pkbf2(wv[kp * 2 + 1], wv[kp * 2]);
            o.y = pkbf2(wv[kp * 2 + 9], wv[kp * 2 + 8]);
            o.z = pkbf2(rv[kp * 2 + 1], rv[kp * 2]);
            o.w = pkbf2(rv[kp * 2 + 9], rv[kp * 2 + 8]);
            g_wgf[(li * 16 + nt) * 32 + lane] = o;
        }
    } else if (idx < 9 * 8 * 128 + 6 * 128 + KC0 * 56) {
        int id3 = idx - (9 * 8 * 128 + 6 * 128);
        int kc = id3 / 56;
        int n = id3 - kc * 56;
        float wv[16], rv[16];
#pragma unroll
        for (int kk = 0; kk < 16; kk++) {
            int k = kc * 16 + kk;
            float v = (k < 1433) ? w_feat[k * 56 + n] : 0.f;
            wv[kk] = v;
            rv[kk] = bfres(v);
        }
        int nt = n >> 3;
#pragma unroll
        for (int kp = 0; kp < 4; kp++) {
            int lane = (n & 7) * 4 + kp;
            uint4 o;
            o.x = pkbf2(wv[kp * 2 + 1], wv[kp * 2]);
            o.y = pkbf2(wv[kp * 2 + 9], wv[kp * 2 + 8]);
            o.z = pkbf2(rv[kp * 2 + 1], rv[kp * 2]);
            o.w = pkbf2(rv[kp * 2 + 9], rv[kp * 2 + 8]);
            g_wff[(kc * 7 + nt) * 32 + lane] = o;
        }
    } else if (idx < 9 * 8 * 128 + 6 * 128 + KC0 * 56 + 4 * 128) {
        // gcn0_w[0] (56x128), k padded to 64: 4 kc chunks
        int id4 = idx - (9 * 8 * 128 + 6 * 128 + KC0 * 56);
        int kc = id4 >> 7;
        int n = id4 & 127;
        float wv[16], rv[16];
#pragma unroll
        for (int kk = 0; kk < 16; kk++) {
            int k = kc * 16 + kk;
            float v = (k < 56) ? gcn0_w[k * 128 + n] : 0.f;
            wv[kk] = v;
            rv[kk] = bfres(v);
        }
        int nt = n >> 3;
#pragma unroll
        for (int kp = 0; kp < 4; kp++) {
            int lane = (n & 7) * 4 + kp;
            uint4 o;
            o.x = pkbf2(wv[kp * 2 + 1], wv[kp * 2]);
            o.y = pkbf2(wv[kp * 2 + 9], wv[kp * 2 + 8]);
            o.z = pkbf2(rv[kp * 2 + 1], rv[kp * 2]);
            o.w = pkbf2(rv[kp * 2 + 9], rv[kp * 2 + 8]);
            g_wg56[(kc * 16 + nt) * 32 + lane] = o;
        }
    } else if (idx < 9 * 8 * 128 + 6 * 128 + KC0 * 56 + 4 * 128 + NC) {
        int j = idx - (9 * 8 * 128 + 6 * 128 + KC0 * 56 + 4 * 128);
        float fb = out_b[j];
        float fw[16];
#pragma unroll
        for (int k = 0; k < 16; k++) fw[k] = 0.f;
        for (int t = 0; t < 56; t++) {
            float wv = out_w[t * NC + j];
            fb += mas_b2[t] * wv;
#pragma unroll
            for (int k = 0; k < 16; k++) fw[k] += masW2[k * 56 + t] * wv;
        }
#pragma unroll
        for (int k = 0; k < 16; k++) g_fw[k * NC + j] = fw[k];
        g_fb[j] = fb;
    }
}

// ---------------- prep: mas-fused GCN weights -> frags + bvec (both blocks) -----
__global__ void k_prep(const float* __restrict__ mas_w, const float* __restrict__ mas_b,
                       const float* __restrict__ gcn0_w) {
    int b = blockIdx.x;                    // 0 -> m=1, 1 -> m=2
    const float* masW = mas_w + b * PH * D0;
    const float* mb_p = mas_b + b * D0;
    const float* Wg = gcn0_w + (b + 1) * D0 * DH;
    int li = (b + 1) * NL;
    __shared__ float mw[16 * 56];
    __shared__ float mb[56];
    int j = threadIdx.x;
    for (int i = j; i < 16 * 56; i += 128) mw[i] = masW[i];
    if (j < 56) mb[j] = mb_p[j];
    __syncthreads();
    float accw[16], rw[16];
#pragma unroll
    for (int k = 0; k < 16; k++) accw[k] = 0.f;
    float accb = 0.f;
    for (int t = 0; t < 56; t++) {
        float wv = Wg[t * 128 + j];
        accb += mb[t] * wv;
#pragma unroll
        for (int k = 0; k < 16; k++) accw[k] += mw[k * 56 + t] * wv;
    }
#pragma unroll
    for (int k = 0; k < 16; k++) rw[k] = bfres(accw[k]);
    int nt = j >> 3;
#pragma unroll
    for (int kp = 0; kp < 4; kp++) {
        int lane = (j & 7) * 4 + kp;
        uint4 o;
        o.x = pkbf2(accw[kp * 2 + 1], accw[kp * 2]);
        o.y = pkbf2(accw[kp * 2 + 9], accw[kp * 2 + 8]);
        o.z = pkbf2(rw[kp * 2 + 1], rw[kp * 2]);
        o.w = pkbf2(rw[kp * 2 + 9], rw[kp * 2 + 8]);
        g_wgf[(li * 16 + nt) * 32 + lane] = o;
    }
    g_bvec[b * DH + j] = accb;
}

// ---------------- 56-dim aggregation (warp/dst, unroll 2; GNFE only) ------------
__global__ void k_agg56(const float* __restrict__ in, float* __restrict__ out,
                        const float* __restrict__ bias, int do_relu) {
    int w = (blockIdx.x * blockDim.x + threadIdx.x) >> 5;
    int lane = threadIdx.x & 31;
    if (w >= NPAD) return;
    int c1 = lane + 32;
    float a0 = 0.f, a1 = 0.f;
    if (w < NN) {
        int e0 = g_off[w], e1 = g_off[w + 1];
        int e = e0;
        for (; e + 2 <= e1; e += 2) {
            int s0 = g_srcs[e], s1 = g_srcs[e + 1];
            float m0 = g_norm[e], m1 = g_norm[e + 1];
            const float* r0 = in + s0 * 56;
            const float* r1 = in + s1 * 56;
            a0 += m0 * r0[lane] + m1 * r1[lane];
            if (c1 < 56) a1 += m0 * r0[c1] + m1 * r1[c1];
        }
        if (e < e1) {
            int s0 = g_srcs[e];
            float m0 = g_norm[e];
            const float* r0 = in + s0 * 56;
            a0 += m0 * r0[lane];
            if (c1 < 56) a1 += m0 * r0[c1];
        }
    }
    float b0 = bias ? bias[lane] : 0.f;
    float v0 = a0 + b0;
    if (do_relu) v0 = fmaxf(v0, 0.f);
    out[w * 56 + lane] = v0;
    if (c1 < 56) {
        float b1 = bias ? bias[c1] : 0.f;
        float v1 = a1 + b1;
        if (do_relu) v1 = fmaxf(v1, 0.f);
        out[w * 56 + c1] = v1;
    }
}

// ---------------- tensor-core fused AGG16 + GCN(16->128) + GAT(128->128) --------
#define HS 136  // smem row stride (bf16), conflict-free for ldmatrix
__global__ __launch_bounds__(256)
void k_fused_mma(const float* __restrict__ hin,
                 const uint4* __restrict__ wgf, const float* __restrict__ bg,
                 const float* __restrict__ bvec,
                 const uint4* __restrict__ wtf,
                 const float* __restrict__ asrc, const float* __restrict__ adst) {
    __shared__ __align__(16) float sAgg[64 * 16];
    __shared__ __align__(16) __nv_bfloat16 sHh[64 * HS];
    __shared__ __align__(16) __nv_bfloat16 sHl[64 * HS];
    int tid = threadIdx.x;
    int lane = tid & 31;
    int wid = tid >> 5;
    int n0 = blockIdx.x * 64;

    // ---- agg phase ----
    {
        int dl = wid * 8 + (lane >> 2);
        int d = n0 + dl;
        int c4 = (lane & 3) * 4;
        float4 a = make_float4(0.f, 0.f, 0.f, 0.f);
        if (d < NN) {
            int e0 = g_off[d], e1 = g_off[d + 1];
            for (int e = e0; e < e1; e += 2) {
                int i1 = (e + 1 < e1) ? e + 1 : e;
                int s0 = g_srcs[e], s1 = g_srcs[i1];
                float m0 = g_norm[e];
                float m1 = (e + 1 < e1) ? g_norm[i1] : 0.f;
                float4 h0 = *(const float4*)(hin + s0 * 16 + c4);
                float4 h1 = *(const float4*)(hin + s1 * 16 + c4);
                a.x += m0 * h0.x + m1 * h1.x;
                a.y += m0 * h0.y + m1 * h1.y;
                a.z += m0 * h0.z + m1 * h1.z;
                a.w += m0 * h0.w + m1 * h1.w;
            }
        }
        *(float4*)&sAgg[dl * 16 + c4] = a;
    }
    __syncthreads();

    int warp_m = wid & 3;
    int warp_n = wid >> 2;
    int rl = warp_m * 16 + (lane >> 2);
    int r = n0 + rl;
    int kq = (lane & 3) * 2;

    const float* ap = sAgg + rl * 16;
    float2 a00 = *(const float2*)(ap + kq);
    float2 a10 = *(const float2*)(ap + 8 * 16 + kq);
    float2 a02 = *(const float2*)(ap + kq + 8);
    float2 a12 = *(const float2*)(ap + 8 * 16 + kq + 8);
    uint32_t ah[4], al[4];
    ah[0] = pkbf2(a00.y, a00.x); al[0] = pkbf2(bfres(a00.y), bfres(a00.x));
    ah[1] = pkbf2(a10.y, a10.x); al[1] = pkbf2(bfres(a10.y), bfres(a10.x));
    ah[2] = pkbf2(a02.y, a02.x); al[2] = pkbf2(bfres(a02.y), bfres(a02.x));
    ah[3] = pkbf2(a12.y, a12.x); al[3] = pkbf2(bfres(a12.y), bfres(a12.x));

    float acc[8][4];
#pragma unroll
    for (int t = 0; t < 8; t++)
        acc[t][0] = acc[t][1] = acc[t][2] = acc[t][3] = 0.f;
#pragma unroll
    for (int t = 0; t < 8; t++) {
        uint4 b = wgf[(warp_n * 8 + t) * 32 + lane];
        mma16816(acc[t], ah, b.x, b.y);
        mma16816(acc[t], ah, b.z, b.w);
        mma16816(acc[t], al, b.x, b.y);
    }

    float ns0 = 0.f, ns1 = 0.f;
    if (bvec) { ns0 = g_nsum[r]; ns1 = g_nsum[r + 8]; }
#pragma unroll
    for (int t = 0; t < 8; t++) {
        int c = warp_n * 64 + t * 8 + kq;
        float b0 = bg[c], b1 = bg[c + 1];
        float v0 = acc[t][0] + b0, v1 = acc[t][1] + b1;
        float v2 = acc[t][2] + b0, v3 = acc[t][3] + b1;
        if (bvec) {
            float bv0 = bvec[c], bv1 = bvec[c + 1];
            v0 += ns0 * bv0; v1 += ns0 * bv1;
            v2 += ns1 * bv0; v3 += ns1 * bv1;
        }
        v0 = fmaxf(v0, 0.f); v1 = fmaxf(v1, 0.f);
        v2 = fmaxf(v2, 0.f); v3 = fmaxf(v3, 0.f);
        int ro = rl * HS + c;
        *(uint32_t*)&sHh[ro] = pkbf2(v1, v0);
        *(uint32_t*)&sHl[ro] = pkbf2(bfres(v1), bfres(v0));
        *(uint32_t*)&sHh[ro + 8 * HS] = pkbf2(v3, v2);
        *(uint32_t*)&sHl[ro + 8 * HS] = pkbf2(bfres(v3), bfres(v2));
    }
    __syncthreads();

#pragma unroll
    for (int t = 0; t < 8; t++)
        acc[t][0] = acc[t][1] = acc[t][2] = acc[t][3] = 0.f;
    uint32_t baseHh = (uint32_t)__cvta_generic_to_shared(sHh);
    uint32_t baseHl = (uint32_t)__cvta_generic_to_shared(sHl);
    int arow = warp_m * 16 + (lane & 15);
#pragma unroll
    for (int kc = 0; kc < 8; kc++) {
        int acol = kc * 16 + (lane >> 4) * 8;
        uint32_t off = (arow * HS + acol) * 2;
        uint32_t a2h[4], a2l[4];
        ldm_x4(a2h[0], a2h[1], a2h[2], a2h[3], baseHh + off);
        ldm_x4(a2l[0], a2l[1], a2l[2], a2l[3], baseHl + off);
        const uint4* wp = wtf + kc * 16 * 32;
#pragma unroll
        for (int t = 0; t < 8; t++) {
            uint4 b = wp[(warp_n * 8 + t) * 32 + lane];
            mma16816(acc[t], a2h, b.x, b.y);
            mma16816(acc[t], a2h, b.z, b.w);
            mma16816(acc[t], a2l, b.x, b.y);
        }
    }

    float* row0p = g_x2 + r * 128;
    float* row1p = g_x2 + (r + 8) * 128;
#pragma unroll
    for (int h2 = 0; h2 < 4; h2++) {
        int head = warp_n * 4 + h2;
        float vs0 = 0.f, vs1 = 0.f, vd0 = 0.f, vd1 = 0.f;
#pragma unroll
        for (int q = 0; q < 2; q++) {
            int t = 2 * h2 + q;
            int c = warp_n * 64 + t * 8 + kq;
            float av0 = asrc[c], av1 = asrc[c + 1];
            float dv0 = adst[c], dv1 = adst[c + 1];
            float c0 = acc[t][0], c1 = acc[t][1], c2 = acc[t][2], c3 = acc[t][3];
            *(float2*)(row0p + c) = make_float2(c0, c1);
            *(float2*)(row1p + c) = make_float2(c2, c3);
            vs0 += c0 * av0 + c1 * av1;
            vs1 += c2 * av0 + c3 * av1;
            vd0 += c0 * dv0 + c1 * dv1;
            vd1 += c2 * dv0 + c3 * dv1;
        }
        vs0 += __shfl_xor_sync(0xffffffffu, vs0, 1);
        vs0 += __shfl_xor_sync(0xffffffffu, vs0, 2);
        vs1 += __shfl_xor_sync(0xffffffffu, vs1, 1);
        vs1 += __shfl_xor_sync(0xffffffffu, vs1, 2);
        vd0 += __shfl_xor_sync(0xffffffffu, vd0, 1);
        vd0 += __shfl_xor_sync(0xffffffffu, vd0, 2);
        vd1 += __shfl_xor_sync(0xffffffffu, vd1, 1);
        vd1 += __shfl_xor_sync(0xffffffffu, vd1, 2);
        if ((lane & 3) == 0) {
            g_es[r * NH + head] = vs0;
            g_es[(r + 8) * NH + head] = vs1;
            g_ed[r * NH + head] = vd0;
            g_ed[(r + 8) * NH + head] = vd1;
        }
    }
}

// ---------------- tensor-core fused AGG56 + GCN(56->128) + GAT (layer 0,0) ------
// smem: sAgg (64x64 fp32, 16KB) aliased over sHh/sHl (34KB total).
__global__ __launch_bounds__(256)
void k_fused_mma56(const float* __restrict__ hin,
                   const uint4* __restrict__ wg56, const float* __restrict__ bg,
                   const uint4* __restrict__ wtf,
                   const float* __restrict__ asrc, const float* __restrict__ adst) {
    __shared__ __align__(16) char smraw[64 * HS * 2 * 2];
    float* sAgg = (float*)smraw;                         // 64*64 fp32 = 16384 B
    __nv_bfloat16* sHh = (__nv_bfloat16*)smraw;          // 64*HS
    __nv_bfloat16* sHl = (__nv_bfloat16*)(smraw + 64 * HS * 2);
    int tid = threadIdx.x;
    int lane = tid & 31;
    int wid = tid >> 5;
    int n0 = blockIdx.x * 64;

    // ---- agg phase: warp handles 8 dsts sequentially (56-dim, k_agg56 inner) ----
    {
        int c1 = lane + 32;
        for (int s = 0; s < 8; s++) {
            int dl = wid * 8 + s;
            int d = n0 + dl;
            float a0 = 0.f, a1 = 0.f;
            if (d < NN) {
                int e0 = g_off[d], e1v = g_off[d + 1];
                int e = e0;
                for (; e + 2 <= e1v; e += 2) {
                    int s0 = g_srcs[e], s1 = g_srcs[e + 1];
                    float m0 = g_norm[e], m1 = g_norm[e + 1];
                    const float* r0 = hin + s0 * 56;
                    const float* r1 = hin + s1 * 56;
                    a0 += m0 * r0[lane] + m1 * r1[lane];
                    if (c1 < 56) a1 += m0 * r0[c1] + m1 * r1[c1];
                }
                if (e < e1v) {
                    int s0 = g_srcs[e];
                    float m0 = g_norm[e];
                    const float* r0 = hin + s0 * 56;
                    a0 += m0 * r0[lane];
                    if (c1 < 56) a1 += m0 * r0[c1];
                }
            }
            sAgg[dl * 64 + lane] = a0;
            sAgg[dl * 64 + c1] = (c1 < 56) ? a1 : 0.f;  // zero pad cols 56..63
        }
    }
    __syncthreads();

    int warp_m = wid & 3;
    int warp_n = wid >> 2;
    int rl = warp_m * 16 + (lane >> 2);
    int r = n0 + rl;
    int kq = (lane & 3) * 2;

    // hoist all GEMM1 A fragments (4 kc chunks) before smem reuse
    uint32_t ah[4][4], al[4][4];
#pragma unroll
    for (int kc = 0; kc < 4; kc++) {
        const float* ap = sAgg + rl * 64 + kc * 16;
        float2 a00 = *(const float2*)(ap + kq);
        float2 a10 = *(const float2*)(ap + 8 * 64 + kq);
        float2 a02 = *(const float2*)(ap + kq + 8);
        float2 a12 = *(const float2*)(ap + 8 * 64 + kq + 8);
        ah[kc][0] = pkbf2(a00.y, a00.x); al[kc][0] = pkbf2(bfres(a00.y), bfres(a00.x));
        ah[kc][1] = pkbf2(a10.y, a10.x); al[kc][1] = pkbf2(bfres(a10.y), bfres(a10.x));
        ah[kc][2] = pkbf2(a02.y, a02.x); al[kc][2] = pkbf2(bfres(a02.y), bfres(a02.x));
        ah[kc][3] = pkbf2(a12.y, a12.x); al[kc][3] = pkbf2(bfres(a12.y), bfres(a12.x));
    }
    __syncthreads();   // sAgg dead; smem becomes sHh/sHl

    float acc[8][4];
#pragma unroll
    for (int t = 0; t < 8; t++)
        acc[t][0] = acc[t][1] = acc[t][2] = acc[t][3] = 0.f;
#pragma unroll
    for (int kc = 0; kc < 4; kc++) {
        const uint4* wp = wg56 + kc * 16 * 32;
#pragma unroll
        for (int t = 0; t < 8; t++) {
            uint4 b = wp[(warp_n * 8 + t) * 32 + lane];
            mma16816(acc[t], ah[kc], b.x, b.y);
            mma16816(acc[t], ah[kc], b.z, b.w);
            mma16816(acc[t], al[kc], b.x, b.y);
        }
    }

    // epilogue 1: bias + relu -> smem split-bf16
#pragma unroll
    for (int t = 0; t < 8; t++) {
        int c = warp_n * 64 + t * 8 + kq;
        float b0 = bg[c], b1 = bg[c + 1];
        float v0 = fmaxf(acc[t][0] + b0, 0.f), v1 = fmaxf(acc[t][1] + b1, 0.f);
        float v2 = fmaxf(acc[t][2] + b0, 0.f), v3 = fmaxf(acc[t][3] + b1, 0.f);
        int ro = rl * HS + c;
        *(uint32_t*)&sHh[ro] = pkbf2(v1, v0);
        *(uint32_t*)&sHl[ro] = pkbf2(bfres(v1), bfres(v0));
        *(uint32_t*)&sHh[ro + 8 * HS] = pkbf2(v3, v2);
        *(uint32_t*)&sHl[ro + 8 * HS] = pkbf2(bfres(v3), bfres(v2));
    }
    __syncthreads();

    // GEMM2: hh = h @ Wt
#pragma unroll
    for (int t = 0; t < 8; t++)
        acc[t][0] = acc[t][1] = acc[t][2] = acc[t][3] = 0.f;
    uint32_t baseHh = (uint32_t)__cvta_generic_to_shared(sHh);
    uint32_t baseHl = (uint32_t)__cvta_generic_to_shared(sHl);
    int arow = warp_m * 16 + (lane & 15);
#pragma unroll
    for (int kc = 0; kc < 8; kc++) {
        int acol = kc * 16 + (lane >> 4) * 8;
        uint32_t off = (arow * HS + acol) * 2;
        uint32_t a2h[4], a2l[4];
        ldm_x4(a2h[0], a2h[1], a2h[2], a2h[3], baseHh + off);
        ldm_x4(a2l[0], a2l[1], a2l[2], a2l[3], baseHl + off);
        const uint4* wp = wtf + kc * 16 * 32;
#pragma unroll
        for (int t = 0; t < 8; t++) {
            uint4 b = wp[(warp_n * 8 + t) * 32 + lane];
            mma16816(acc[t], a2h, b.x, b.y);
            mma16816(acc[t], a2h, b.z, b.w);
            mma16816(acc[t], a2l, b.x, b.y);
        }
    }

    // epilogue 2: store hh + es/ed
    float* row0p = g_x2 + r * 128;
    float* row1p = g_x2 + (r + 8) * 128;
#pragma unroll
    for (int h2 = 0; h2 < 4; h2++) {
        int head = warp_n * 4 + h2;
        float vs0 = 0.f, vs1 = 0.f, vd0 = 0.f, vd1 = 0.f;
#pragma unroll
        for (int q = 0; q < 2; q++) {
            int t = 2 * h2 + q;
            int c = warp_n * 64 + t * 8 + kq;
            float av0 = asrc[c], av1 = asrc[c + 1];
            float dv0 = adst[c], dv1 = adst[c + 1];
            float c0 = acc[t][0], c1 = acc[t][1], c2 = acc[t][2], c3 = acc[t][3];
            *(float2*)(row0p + c) = make_float2(c0, c1);
            *(float2*)(row1p + c) = make_float2(c2, c3);
            vs0 += c0 * av0 + c1 * av1;
            vs1 += c2 * av0 + c3 * av1;
            vd0 += c0 * dv0 + c1 * dv1;
            vd1 += c2 * dv0 + c3 * dv1;
        }
        vs0 += __shfl_xor_sync(0xffffffffu, vs0, 1);
        vs0 += __shfl_xor_sync(0xffffffffu, vs0, 2);
        vs1 += __shfl_xor_sync(0xffffffffu, vs1, 1);
        vs1 += __shfl_xor_sync(0xffffffffu, vs1, 2);
        vd0 += __shfl_xor_sync(0xffffffffu, vd0, 1);
        vd0 += __shfl_xor_sync(0xffffffffu, vd0, 2);
        vd1 += __shfl_xor_sync(0xffffffffu, vd1, 1);
        vd1 += __shfl_xor_sync(0xffffffffu, vd1, 2);
        if ((lane & 3) == 0) {
            g_es[r * NH + head] = vs0;
            g_es[(r + 8) * NH + head] = vs1;
            g_ed[r * NH + head] = vd0;
            g_ed[(r + 8) * NH + head] = vd1;
        }
    }
}

// ---------------- single-pass GAT edge aggregation (R14 proven form) -------------
__global__ void k_gat_edge(const float* __restrict__ gb) {
    int w = (blockIdx.x * blockDim.x + threadIdx.x) >> 5;
    int lane = threadIdx.x & 31;
    if (w >= NN) return;
    int h8 = lane & 7;
    int eg = lane >> 3;
    int hsel = lane >> 2;
    float edh = g_ed[w * NH + h8];
    int e0 = g_off[w], e1 = g_off[w + 1];
    unsigned long long acc01 = 0ull, acc23 = 0ull;
    float dsum = 0.f;
    for (int e = e0; e < e1; e += 4) {
        int ee = e + eg;
        int idx = ee < e1 ? ee : e1 - 1;
        int soff = g_srcs[idx] << 7;
        float v = g_es[(soff >> 4) + h8] + edh;
        v = fmaxf(v, 0.2f * v);
        float wv = (ee < e1) ? __expf(v) : 0.f;
        dsum += wv;
#pragma unroll
        for (int q = 0; q < 4; q++) {
            float wb = __shfl_sync(0xffffffffu, wv, q * 8 + hsel);
            int so = __shfl_sync(0xffffffffu, soff, q * 8);
            unsigned long long wb2;
            PACKW(wb2, wb);
            ulonglong2 hv = reinterpret_cast<const ulonglong2*>(g_x2 + so)[lane];
            FFMA2(acc01, hv.x, wb2);
            FFMA2(acc23, hv.y, wb2);
        }
    }
    dsum += __shfl_xor_sync(0xffffffffu, dsum, 8);
    dsum += __shfl_xor_sync(0xffffffffu, dsum, 16);
    float db = __shfl_sync(0xffffffffu, dsum, hsel);
    float inv = 1.f / db;
    float4 acc;
    UNPK(acc.x, acc.y, acc01);
    UNPK(acc.z, acc.w, acc23);
    acc.x *= inv; acc.y *= inv; acc.z *= inv; acc.w *= inv;
#pragma unroll
    for (int off = 4; off <= 16; off <<= 1) {
        acc.x += __shfl_xor_sync(0xffffffffu, acc.x, off);
        acc.y += __shfl_xor_sync(0xffffffffu, acc.y, off);
        acc.z += __shfl_xor_sync(0xffffffffu, acc.z, off);
        acc.w += __shfl_xor_sync(0xffffffffu, acc.w, off);
    }
    if (lane < 4) {
        float4 gb4 = reinterpret_cast<const float4*>(gb)[lane];
        float4 r;
        r.x = acc.x * 0.125f + gb4.x;
        r.y = acc.y * 0.125f + gb4.y;
        r.z = acc.z * 0.125f + gb4.z;
        r.w = acc.w * 0.125f + gb4.w;
        reinterpret_cast<float4*>(g_hA + w * PH)[lane] = r;
    }
}

// ---------------- fused MAS+output ----------------
__global__ void k_masout(float* __restrict__ out) {
    int t = blockIdx.x * blockDim.x + threadIdx.x;
    if (t >= NN * NC) return;
    int n = t / NC, c = t - n * NC;
    float acc = g_fb[c];
    const float* hr = g_hA + n * PH;
#pragma unroll
    for (int k = 0; k < 16; k++) acc += hr[k] * g_fw[k * NC + c];
    out[t] = acc;
}

// ---------------- launcher ----------------
extern "C" void kernel_launch(void* const* d_in, const int* in_sizes, int n_in,
                              void* d_out, int out_size) {
    const float* x      = (const float*)d_in[0];
    const int*   ei     = (const int*)d_in[1];
    const float* w_feat = (const float*)d_in[2];
    const float* b_feat = (const float*)d_in[3];
    const float* gcn0_w = (const float*)d_in[4];
    const float* gcn0_b = (const float*)d_in[5];
    const float* gcn_w  = (const float*)d_in[6];
    const float* gcn_b  = (const float*)d_in[7];
    const float* gat_w  = (const float*)d_in[8];
    const float* gat_as = (const float*)d_in[9];
    const float* gat_ad = (const float*)d_in[10];
    const float* gat_b  = (const float*)d_in[11];
    const float* mas_w  = (const float*)d_in[12];
    const float* mas_b  = (const float*)d_in[13];
    const float* out_w  = (const float*)d_in[14];
    const float* out_b  = (const float*)d_in[15];
    float* out = (float*)d_out;
    (void)in_sizes; (void)n_in; (void)out_size;

    float *p_x1, *p_hA, *p_hB, *p_bvec;
    uint4 *p_wtf, *p_wgf, *p_wg56;
    cudaGetSymbolAddress((void**)&p_x1, g_x1);
    cudaGetSymbolAddress((void**)&p_hA, g_hA);
    cudaGetSymbolAddress((void**)&p_hB, g_hB);
    cudaGetSymbolAddress((void**)&p_bvec, g_bvec);
    cudaGetSymbolAddress((void**)&p_wtf, g_wtf);
    cudaGetSymbolAddress((void**)&p_wgf, g_wgf);
    cudaGetSymbolAddress((void**)&p_wg56, g_wg56);

    // weights prep + CSR build; gemm0 at capture slot #4
    k_deg_count<<<(EE + 255) / 256, 256>>>(ei);
    k_swz<<<(9 * 8 * 128 + 6 * 128 + KC0 * 56 + 4 * 128 + NC + 255) / 256, 256>>>(
        gat_w, gcn_w, w_feat, gcn0_w,
        mas_w + 2 * PH * D0, mas_b + 2 * D0, out_w, out_b);
    k_prep<<<2, 128>>>(mas_w, mas_b, gcn0_w);
    k_gemm0<<<(NN + 127) / 128, 256>>>(x);
    k_scan1<<<NB_SCAN, 256>>>();
    k_scan2<<<1, 256>>>();
    k_scan3<<<NB_SCAN, 256>>>();
    k_fill<<<(ENT + 255) / 256, 256>>>(ei);

    // GNFE: aggregate transformed features (+bias, relu)
    k_agg56<<<NPAD / 8, 256>>>(p_x1, p_hB, b_feat, 1);

    for (int m = 0; m < NL; m++) {
        for (int i = 0; i < NL; i++) {
            int li = m * NL + i;
            const float* as = gat_as + li * NH * PH;
            const float* ad = gat_ad + li * NH * PH;
            const uint4* wtf = p_wtf + li * 8 * 16 * 32;
            if (i == 0 && m == 0) {
                k_fused_mma56<<<NPAD / 64, 256>>>(p_hB, p_wg56, gcn0_b, wtf, as, ad);
            } else if (i == 0) {
                k_fused_mma<<<NPAD / 64, 256>>>(p_hA, p_wgf + li * 16 * 32,
                                                gcn0_b + m * DH,
                                                p_bvec + (m - 1) * DH, wtf, as, ad);
            } else {
                k_fused_mma<<<NPAD / 64, 256>>>(
                    p_hA, p_wgf + li * 16 * 32,
                    gcn_b + (m * (NL - 1) + (i - 1)) * DH,
                    (const float*)0, wtf, as, ad);
            }
            k_gat_edge<<<(NN * 32 + 255) / 256, 256>>>(gat_b + li * PH);
        }
    }
    k_masout<<<(NN * NC + 255) / 256, 256>>>(out);
}

// round 17
// speedup vs baseline: 1.1242x; 1.0353x over previous
#include <cuda_runtime.h>
#include <cuda_bf16.h>
#include <math.h>
#include <stdint.h>

#define NN 50000
#define NPAD 50048
#define EE 800000
#define ENT (EE + NN)
#define NH 8
#define PH 16
#define DH 128
#define D0 56
#define NC 7
#define NL 3
#define NB_SCAN 196  // ceil(50000/256)
#define KC0 90       // ceil(1433/16) k-chunks for gemm0

// packed fp32x2 FMA (sm_103a)
#define FFMA2(acc, h, w) \
    asm("fma.rn.f32x2 %0, %1, %2, %0;" : "+l"(acc) : "l"(h), "l"(w))
#define PACKW(dst, f) \
    asm("mov.b64 %0, {%1, %1};" : "=l"(dst) : "r"(__float_as_uint(f)))
#define UNPK(lo, hi, v) \
    do { unsigned int _a, _b; \
         asm("mov.b64 {%0,%1}, %2;" : "=r"(_a), "=r"(_b) : "l"(v)); \
         lo = __uint_as_float(_a); hi = __uint_as_float(_b); } while (0)

__device__ __forceinline__ uint32_t pkbf2(float hi, float lo) {
    uint32_t d;
    asm("cvt.rn.bf16x2.f32 %0, %1, %2;" : "=r"(d) : "f"(hi), "f"(lo));
    return d;
}
__device__ __forceinline__ float bfres(float v) {
    return v - __bfloat162float(__float2bfloat16(v));
}
__device__ __forceinline__ void mma16816(float* c, const uint32_t* a,
                                         uint32_t b0, uint32_t b1) {
    asm volatile(
        "mma.sync.aligned.m16n8k16.row.col.f32.bf16.bf16.f32 "
        "{%0,%1,%2,%3}, {%4,%5,%6,%7}, {%8,%9}, {%0,%1,%2,%3};"
        : "+f"(c[0]), "+f"(c[1]), "+f"(c[2]), "+f"(c[3])
        : "r"(a[0]), "r"(a[1]), "r"(a[2]), "r"(a[3]), "r"(b0), "r"(b1));
}
__device__ __forceinline__ void ldm_x4(uint32_t& r0, uint32_t& r1, uint32_t& r2,
                                       uint32_t& r3, uint32_t addr) {
    asm volatile("ldmatrix.sync.aligned.m8n8.x4.shared.b16 {%0,%1,%2,%3}, [%4];"
                 : "=r"(r0), "=r"(r1), "=r"(r2), "=r"(r3) : "r"(addr));
}

// ---------------- scratch ----------------
__device__ int   g_deg[NN];
__device__ int   g_off[NN + 1];
__device__ int   g_cur[NN];
__device__ int   g_part[256];
__device__ int   g_srcs[ENT + 8];
__device__ float g_norm[ENT + 8];
__device__ float g_dinv[NN];
__device__ float g_nsum[NPAD];
__device__ float g_hB[NPAD * D0];
__device__ float g_hA[NPAD * PH];
__device__ float g_x1[NPAD * D0];
__device__ float g_x2[NPAD * DH];
__device__ float g_es[NPAD * NH];
__device__ float g_ed[NPAD * NH];
__device__ float g_bvec[2 * DH];
__device__ float g_fw[PH * NC];
__device__ float g_fb[NC];
__device__ uint4 g_wtf[9 * 8 * 16 * 32];  // GAT W frags: [li][kc][nt][lane]
__device__ uint4 g_wgf[9 * 16 * 32];      // GCN W frags (k=16): [li][nt][lane]
__device__ uint4 g_wff[KC0 * 7 * 32];     // w_feat frags: [kc][nt][lane]
__device__ uint4 g_wg56[4 * 16 * 32];     // gcn0_w[0] frags (56->64 pad)

// ---------------- CSR construction ----------------
__global__ void k_deg_count(const int* __restrict__ ei) {
    int e = blockIdx.x * blockDim.x + threadIdx.x;
    if (e < EE) atomicAdd(&g_deg[ei[EE + e]], 1);
}

__global__ void k_scan1() {
    __shared__ int sh[256];
    int t = threadIdx.x;
    int i = blockIdx.x * 256 + t;
    int d = (i < NN) ? g_deg[i] + 1 : 0;   // +1 self-loop
    sh[t] = d;
    __syncthreads();
#pragma unroll
    for (int off = 1; off < 256; off <<= 1) {
        int v = (t >= off) ? sh[t - off] : 0;
        __syncthreads();
        sh[t] += v;
        __syncthreads();
    }
    if (t == 255) g_part[blockIdx.x] = sh[255];
    if (i < NN) g_off[i] = sh[t] - d;
}

// scan2 merged in: each block reduces the partials below it
__global__ void k_scan3() {
    __shared__ int warpsum[8];
    __shared__ int sbase;
    int b = blockIdx.x;
    int t = threadIdx.x;
    int v = (t < b) ? g_part[t] : 0;   // b <= 195 < 256
#pragma unroll
    for (int o = 16; o > 0; o >>= 1) v += __shfl_xor_sync(0xffffffffu, v, o);
    if ((t & 31) == 0) warpsum[t >> 5] = v;
    __syncthreads();
    if (t == 0) {
        int s = 0;
#pragma unroll
        for (int k = 0; k < 8; k++) s += warpsum[k];
        sbase = s;
    }
    __syncthreads();
    int i = b * 256 + t;
    if (i >= NN) return;
    int off = g_off[i] + sbase;
    g_off[i] = off;
    g_cur[i] = off;
    g_dinv[i] = rsqrtf((float)(g_deg[i] + 1));
    g_deg[i] = 0;        // reset for next replay (graph capture)
    if (i == 0) g_off[NN] = ENT;
}

__global__ void k_fill(const int* __restrict__ ei) {
    int e = blockIdx.x * blockDim.x + threadIdx.x;
    if (e >= ENT) return;
    int s, d;
    if (e < EE) { s = ei[e]; d = ei[EE + e]; }
    else        { s = d = e - EE; }
    int p = atomicAdd(&g_cur[d], 1);
    g_srcs[p] = s;
    g_norm[p] = g_dinv[s] * g_dinv[d];
}

// ---------------- smem-free tensor-core GEMM0 (R11 proven version) -------------
__device__ __forceinline__ void g0_load(const float* xp1, const float* xp2,
                                        bool p1, bool p2, int kb, float* v) {
    v[0] = p1 ? xp1[kb]     : 0.f;
    v[1] = p1 ? xp1[kb + 1] : 0.f;
    v[2] = p1 ? xp1[kb + 8] : 0.f;
    v[3] = p1 ? xp1[kb + 9] : 0.f;
    v[4] = p2 ? xp2[kb]     : 0.f;
    v[5] = p2 ? xp2[kb + 1] : 0.f;
    v[6] = p2 ? xp2[kb + 8] : 0.f;
    v[7] = p2 ? xp2[kb + 9] : 0.f;
}
__device__ __forceinline__ void g0_mma(const float* v, const uint4* wp,
                                       float acc[7][4]) {
    uint32_t ah[4], al[4];
    ah[0] = pkbf2(v[1], v[0]); al[0] = pkbf2(bfres(v[1]), bfres(v[0]));
    ah[1] = pkbf2(v[5], v[4]); al[1] = pkbf2(bfres(v[5]), bfres(v[4]));
    ah[2] = pkbf2(v[3], v[2]); al[2] = pkbf2(bfres(v[3]), bfres(v[2]));
    ah[3] = pkbf2(v[7], v[6]); al[3] = pkbf2(bfres(v[7]), bfres(v[6]));
#pragma unroll
    for (int nt = 0; nt < 7; nt++) {
        uint4 b = wp[nt * 32];
        mma16816(acc[nt], ah, b.x, b.y);
        mma16816(acc[nt], ah, b.z, b.w);
        mma16816(acc[nt], al, b.x, b.y);
    }
}

__global__ __launch_bounds__(256)
void k_gemm0(const float* __restrict__ x) {
    int tid = threadIdx.x;
    int lane = tid & 31;
    int wid = tid >> 5;
    int row0 = blockIdx.x * 128;
    int r1 = row0 + wid * 16 + (lane >> 2);
    int r2 = r1 + 8;
    int kq = (lane & 3) * 2;
    bool p1 = r1 < NN, p2 = r2 < NN;
    const float* xp1 = x + (int64_t)r1 * 1433 + kq;
    const float* xp2 = x + (int64_t)r2 * 1433 + kq;

    float acc[7][4];
#pragma unroll
    for (int nt = 0; nt < 7; nt++)
        acc[nt][0] = acc[nt][1] = acc[nt][2] = acc[nt][3] = 0.f;

    const uint4* wbase = g_wff + lane;

    int kc = 0;
    for (; kc + 2 <= KC0 - 1; kc += 2) {
        float va[8], vb[8];
        g0_load(xp1, xp2, p1, p2, kc * 16, va);
        g0_load(xp1, xp2, p1, p2, kc * 16 + 16, vb);
        g0_mma(va, wbase + kc * 7 * 32, acc);
        g0_mma(vb, wbase + (kc + 1) * 7 * 32, acc);
    }
    {
        float va[8];
        g0_load(xp1, xp2, p1, p2, kc * 16, va);
        g0_mma(va, wbase + kc * 7 * 32, acc);
    }
    {
        const int kb = (KC0 - 1) * 16;
        float v[8];
        v[0] = p1 ? xp1[kb]     : 0.f;
        v[1] = p1 ? xp1[kb + 1] : 0.f;
        v[2] = (p1 && kq == 0) ? xp1[kb + 8] : 0.f;
        v[3] = 0.f;
        v[4] = p2 ? xp2[kb]     : 0.f;
        v[5] = p2 ? xp2[kb + 1] : 0.f;
        v[6] = (p2 && kq == 0) ? xp2[kb + 8] : 0.f;
        v[7] = 0.f;
        g0_mma(v, wbase + (KC0 - 1) * 7 * 32, acc);
    }

#pragma unroll
    for (int nt = 0; nt < 7; nt++) {
        int col = nt * 8 + kq;
        if (p1) *(float2*)&g_x1[r1 * 56 + col] = make_float2(acc[nt][0], acc[nt][1]);
        if (p2) *(float2*)&g_x1[r2 * 56 + col] = make_float2(acc[nt][2], acc[nt][3]);
    }
}

// ---------------- weight fragment swizzles (+ w_feat, gcn0_w[0], out prep) ------
__global__ void k_swz(const float* __restrict__ gat_w, const float* __restrict__ gcn_w,
                      const float* __restrict__ w_feat, const float* __restrict__ gcn0_w,
                      const float* __restrict__ masW2, const float* __restrict__ mas_b2,
                      const float* __restrict__ out_w, const float* __restrict__ out_b) {
    int idx = blockIdx.x * blockDim.x + threadIdx.x;
    if (idx < 9 * 8 * 128) {
        int li = idx >> 10;
        int rem = idx & 1023;
        int kc = rem >> 7;
        int n = rem & 127;
        const float* W = gat_w + li * 128 * 128;
        float wv[16], rv[16];
#pragma unroll
        for (int kk = 0; kk < 16; kk++) {
            float v = W[(kc * 16 + kk) * 128 + n];
            wv[kk] = v;
            rv[kk] = bfres(v);
        }
        int nt = n >> 3;
#pragma unroll
        for (int kp = 0; kp < 4; kp++) {
            int lane = (n & 7) * 4 + kp;
            uint4 o;
            o.x = pkbf2(wv[kp * 2 + 1], wv[kp * 2]);
            o.y = pkbf2(wv[kp * 2 + 9], wv[kp * 2 + 8]);
            o.z = pkbf2(rv[kp * 2 + 1], rv[kp * 2]);
            o.w = pkbf2(rv[kp * 2 + 9], rv[kp * 2 + 8]);
            g_wtf[((li * 8 + kc) * 16 + nt) * 32 + lane] = o;
        }
    } else if (idx < 9 * 8 * 128 + 6 * 128) {
        int id2 = idx - 9 * 8 * 128;
        int j = id2 >> 7;          // 0..5
        int n = id2 & 127;
        int m = j >> 1, i = 1 + (j & 1);
        int li = m * 3 + i;
        const float* W = gcn_w + (m * 2 + (i - 1)) * 16 * 128;
        float wv[16], rv[16];
#pragma unroll
        for (int kk = 0; kk < 16; kk++) {
            float v = W[kk * 128 + n];
            wv[kk] = v;
            rv[kk] = bfres(v);
        }
        int nt = n >> 3;
#pragma unroll
        for (int kp = 0; kp < 4; kp++) {
            int lane = (n & 7) * 4 + kp;
            uint4 o;
            o.x = pkbf2(wv[kp * 2 + 1], wv[kp * 2]);
            o.y = pkbf2(wv[kp * 2 + 9], wv[kp * 2 + 8]);
            o.z = pkbf2(rv[kp * 2 + 1], rv[kp * 2]);
            o.w = pkbf2(rv[kp * 2 + 9], rv[kp * 2 + 8]);
            g_wgf[(li * 16 + nt) * 32 + lane] = o;
        }
    } else if (idx < 9 * 8 * 128 + 6 * 128 + KC0 * 56) {
        int id3 = idx - (9 * 8 * 128 + 6 * 128);
        int kc = id3 / 56;
        int n = id3 - kc * 56;
        float wv[16], rv[16];
#pragma unroll
        for (int kk = 0; kk < 16; kk++) {
            int k = kc * 16 + kk;
            float v = (k < 1433) ? w_feat[k * 56 + n] : 0.f;
            wv[kk] = v;
            rv[kk] = bfres(v);
        }
        int nt = n >> 3;
#pragma unroll
        for (int kp = 0; kp < 4; kp++) {
            int lane = (n & 7) * 4 + kp;
            uint4 o;
            o.x = pkbf2(wv[kp * 2 + 1], wv[kp * 2]);
            o.y = pkbf2(wv[kp * 2 + 9], wv[kp * 2 + 8]);
            o.z = pkbf2(rv[kp * 2 + 1], rv[kp * 2]);
            o.w = pkbf2(rv[kp * 2 + 9], rv[kp * 2 + 8]);
            g_wff[(kc * 7 + nt) * 32 + lane] = o;
        }
    } else if (idx < 9 * 8 * 128 + 6 * 128 + KC0 * 56 + 4 * 128) {
        int id4 = idx - (9 * 8 * 128 + 6 * 128 + KC0 * 56);
        int kc = id4 >> 7;
        int n = id4 & 127;
        float wv[16], rv[16];
#pragma unroll
        for (int kk = 0; kk < 16; kk++) {
            int k = kc * 16 + kk;
            float v = (k < 56) ? gcn0_w[k * 128 + n] : 0.f;
            wv[kk] = v;
            rv[kk] = bfres(v);
        }
        int nt = n >> 3;
#pragma unroll
        for (int kp = 0; kp < 4; kp++) {
            int lane = (n & 7) * 4 + kp;
            uint4 o;
            o.x = pkbf2(wv[kp * 2 + 1], wv[kp * 2]);
            o.y = pkbf2(wv[kp * 2 + 9], wv[kp * 2 + 8]);
            o.z = pkbf2(rv[kp * 2 + 1], rv[kp * 2]);
            o.w = pkbf2(rv[kp * 2 + 9], rv[kp * 2 + 8]);
            g_wg56[(kc * 16 + nt) * 32 + lane] = o;
        }
    } else if (idx < 9 * 8 * 128 + 6 * 128 + KC0 * 56 + 4 * 128 + NC) {
        int j = idx - (9 * 8 * 128 + 6 * 128 + KC0 * 56 + 4 * 128);
        float fb = out_b[j];
        float fw[16];
#pragma unroll
        for (int k = 0; k < 16; k++) fw[k] = 0.f;
        for (int t = 0; t < 56; t++) {
            float wv = out_w[t * NC + j];
            fb += mas_b2[t] * wv;
#pragma unroll
            for (int k = 0; k < 16; k++) fw[k] += masW2[k * 56 + t] * wv;
        }
#pragma unroll
        for (int k = 0; k < 16; k++) g_fw[k * NC + j] = fw[k];
        g_fb[j] = fb;
    }
}

// ---------------- prep: mas-fused GCN weights -> frags + bvec (both blocks) -----
__global__ void k_prep(const float* __restrict__ mas_w, const float* __restrict__ mas_b,
                       const float* __restrict__ gcn0_w) {
    int b = blockIdx.x;                    // 0 -> m=1, 1 -> m=2
    const float* masW = mas_w + b * PH * D0;
    const float* mb_p = mas_b + b * D0;
    const float* Wg = gcn0_w + (b + 1) * D0 * DH;
    int li = (b + 1) * NL;
    __shared__ float mw[16 * 56];
    __shared__ float mb[56];
    int j = threadIdx.x;
    for (int i = j; i < 16 * 56; i += 128) mw[i] = masW[i];
    if (j < 56) mb[j] = mb_p[j];
    __syncthreads();
    float accw[16], rw[16];
#pragma unroll
    for (int k = 0; k < 16; k++) accw[k] = 0.f;
    float accb = 0.f;
    for (int t = 0; t < 56; t++) {
        float wv = Wg[t * 128 + j];
        accb += mb[t] * wv;
#pragma unroll
        for (int k = 0; k < 16; k++) accw[k] += mw[k * 56 + t] * wv;
    }
#pragma unroll
    for (int k = 0; k < 16; k++) rw[k] = bfres(accw[k]);
    int nt = j >> 3;
#pragma unroll
    for (int kp = 0; kp < 4; kp++) {
        int lane = (j & 7) * 4 + kp;
        uint4 o;
        o.x = pkbf2(accw[kp * 2 + 1], accw[kp * 2]);
        o.y = pkbf2(accw[kp * 2 + 9], accw[kp * 2 + 8]);
        o.z = pkbf2(rw[kp * 2 + 1], rw[kp * 2]);
        o.w = pkbf2(rw[kp * 2 + 9], rw[kp * 2 + 8]);
        g_wgf[(li * 16 + nt) * 32 + lane] = o;
    }
    g_bvec[b * DH + j] = accb;
}

// ---------------- 56-dim aggregation (warp/dst, unroll 2; GNFE only) ------------
__global__ void k_agg56(const float* __restrict__ in, float* __restrict__ out,
                        const float* __restrict__ bias, int do_relu) {
    int w = (blockIdx.x * blockDim.x + threadIdx.x) >> 5;
    int lane = threadIdx.x & 31;
    if (w >= NPAD) return;
    int c1 = lane + 32;
    float a0 = 0.f, a1 = 0.f;
    if (w < NN) {
        int e0 = g_off[w], e1 = g_off[w + 1];
        int e = e0;
        for (; e + 2 <= e1; e += 2) {
            int s0 = g_srcs[e], s1 = g_srcs[e + 1];
            float m0 = g_norm[e], m1 = g_norm[e + 1];
            const float* r0 = in + s0 * 56;
            const float* r1 = in + s1 * 56;
            a0 += m0 * r0[lane] + m1 * r1[lane];
            if (c1 < 56) a1 += m0 * r0[c1] + m1 * r1[c1];
        }
        if (e < e1) {
            int s0 = g_srcs[e];
            float m0 = g_norm[e];
            const float* r0 = in + s0 * 56;
            a0 += m0 * r0[lane];
            if (c1 < 56) a1 += m0 * r0[c1];
        }
    }
    float b0 = bias ? bias[lane] : 0.f;
    float v0 = a0 + b0;
    if (do_relu) v0 = fmaxf(v0, 0.f);
    out[w * 56 + lane] = v0;
    if (c1 < 56) {
        float b1 = bias ? bias[c1] : 0.f;
        float v1 = a1 + b1;
        if (do_relu) v1 = fmaxf(v1, 0.f);
        out[w * 56 + c1] = v1;
    }
}

// ---------------- tensor-core fused AGG16 + GCN(16->128) + GAT(128->128) --------
#define HS 136  // smem row stride (bf16), conflict-free for ldmatrix
__global__ __launch_bounds__(256)
void k_fused_mma(const float* __restrict__ hin,
                 const uint4* __restrict__ wgf, const float* __restrict__ bg,
                 const float* __restrict__ bvec,
                 const uint4* __restrict__ wtf,
                 const float* __restrict__ asrc, const float* __restrict__ adst) {
    __shared__ __align__(16) float sAgg[64 * 16];
    __shared__ __align__(16) __nv_bfloat16 sHh[64 * HS];
    __shared__ __align__(16) __nv_bfloat16 sHl[64 * HS];
    int tid = threadIdx.x;
    int lane = tid & 31;
    int wid = tid >> 5;
    int n0 = blockIdx.x * 64;

    // ---- agg phase ----
    {
        int dl = wid * 8 + (lane >> 2);
        int d = n0 + dl;
        int c4 = (lane & 3) * 4;
        float4 a = make_float4(0.f, 0.f, 0.f, 0.f);
        if (d < NN) {
            int e0 = g_off[d], e1 = g_off[d + 1];
            for (int e = e0; e < e1; e += 2) {
                int i1 = (e + 1 < e1) ? e + 1 : e;
                int s0 = g_srcs[e], s1 = g_srcs[i1];
                float m0 = g_norm[e];
                float m1 = (e + 1 < e1) ? g_norm[i1] : 0.f;
                float4 h0 = *(const float4*)(hin + s0 * 16 + c4);
                float4 h1 = *(const float4*)(hin + s1 * 16 + c4);
                a.x += m0 * h0.x + m1 * h1.x;
                a.y += m0 * h0.y + m1 * h1.y;
                a.z += m0 * h0.z + m1 * h1.z;
                a.w += m0 * h0.w + m1 * h1.w;
            }
        }
        *(float4*)&sAgg[dl * 16 + c4] = a;
    }
    __syncthreads();

    int warp_m = wid & 3;
    int warp_n = wid >> 2;
    int rl = warp_m * 16 + (lane >> 2);
    int r = n0 + rl;
    int kq = (lane & 3) * 2;

    const float* ap = sAgg + rl * 16;
    float2 a00 = *(const float2*)(ap + kq);
    float2 a10 = *(const float2*)(ap + 8 * 16 + kq);
    float2 a02 = *(const float2*)(ap + kq + 8);
    float2 a12 = *(const float2*)(ap + 8 * 16 + kq + 8);
    uint32_t ah[4], al[4];
    ah[0] = pkbf2(a00.y, a00.x); al[0] = pkbf2(bfres(a00.y), bfres(a00.x));
    ah[1] = pkbf2(a10.y, a10.x); al[1] = pkbf2(bfres(a10.y), bfres(a10.x));
    ah[2] = pkbf2(a02.y, a02.x); al[2] = pkbf2(bfres(a02.y), bfres(a02.x));
    ah[3] = pkbf2(a12.y, a12.x); al[3] = pkbf2(bfres(a12.y), bfres(a12.x));

    float acc[8][4];
#pragma unroll
    for (int t = 0; t < 8; t++)
        acc[t][0] = acc[t][1] = acc[t][2] = acc[t][3] = 0.f;
#pragma unroll
    for (int t = 0; t < 8; t++) {
        uint4 b = wgf[(warp_n * 8 + t) * 32 + lane];
        mma16816(acc[t], ah, b.x, b.y);
        mma16816(acc[t], ah, b.z, b.w);
        mma16816(acc[t], al, b.x, b.y);
    }

    float ns0 = 0.f, ns1 = 0.f;
    if (bvec) { ns0 = g_nsum[r]; ns1 = g_nsum[r + 8]; }
#pragma unroll
    for (int t = 0; t < 8; t++) {
        int c = warp_n * 64 + t * 8 + kq;
        float b0 = bg[c], b1 = bg[c + 1];
        float v0 = acc[t][0] + b0, v1 = acc[t][1] + b1;
        float v2 = acc[t][2] + b0, v3 = acc[t][3] + b1;
        if (bvec) {
            float bv0 = bvec[c], bv1 = bvec[c + 1];
            v0 += ns0 * bv0; v1 += ns0 * bv1;
            v2 += ns1 * bv0; v3 += ns1 * bv1;
        }
        v0 = fmaxf(v0, 0.f); v1 = fmaxf(v1, 0.f);
        v2 = fmaxf(v2, 0.f); v3 = fmaxf(v3, 0.f);
        int ro = rl * HS + c;
        *(uint32_t*)&sHh[ro] = pkbf2(v1, v0);
        *(uint32_t*)&sHl[ro] = pkbf2(bfres(v1), bfres(v0));
        *(uint32_t*)&sHh[ro + 8 * HS] = pkbf2(v3, v2);
        *(uint32_t*)&sHl[ro + 8 * HS] = pkbf2(bfres(v3), bfres(v2));
    }
    __syncthreads();

#pragma unroll
    for (int t = 0; t < 8; t++)
        acc[t][0] = acc[t][1] = acc[t][2] = acc[t][3] = 0.f;
    uint32_t baseHh = (uint32_t)__cvta_generic_to_shared(sHh);
    uint32_t baseHl = (uint32_t)__cvta_generic_to_shared(sHl);
    int arow = warp_m * 16 + (lane & 15);
#pragma unroll
    for (int kc = 0; kc < 8; kc++) {
        int acol = kc * 16 + (lane >> 4) * 8;
        uint32_t off = (arow * HS + acol) * 2;
        uint32_t a2h[4], a2l[4];
        ldm_x4(a2h[0], a2h[1], a2h[2], a2h[3], baseHh + off);
        ldm_x4(a2l[0], a2l[1], a2l[2], a2l[3], baseHl + off);
        const uint4* wp = wtf + kc * 16 * 32;
#pragma unroll
        for (int t = 0; t < 8; t++) {
            uint4 b = wp[(warp_n * 8 + t) * 32 + lane];
            mma16816(acc[t], a2h, b.x, b.y);
            mma16816(acc[t], a2h, b.z, b.w);
            mma16816(acc[t], a2l, b.x, b.y);
        }
    }

    float* row0p = g_x2 + r * 128;
    float* row1p = g_x2 + (r + 8) * 128;
#pragma unroll
    for (int h2 = 0; h2 < 4; h2++) {
        int head = warp_n * 4 + h2;
        float vs0 = 0.f, vs1 = 0.f, vd0 = 0.f, vd1 = 0.f;
#pragma unroll
        for (int q = 0; q < 2; q++) {
            int t = 2 * h2 + q;
            int c = warp_n * 64 + t * 8 + kq;
            float av0 = asrc[c], av1 = asrc[c + 1];
            float dv0 = adst[c], dv1 = adst[c + 1];
            float c0 = acc[t][0], c1 = acc[t][1], c2 = acc[t][2], c3 = acc[t][3];
            *(float2*)(row0p + c) = make_float2(c0, c1);
            *(float2*)(row1p + c) = make_float2(c2, c3);
            vs0 += c0 * av0 + c1 * av1;
            vs1 += c2 * av0 + c3 * av1;
            vd0 += c0 * dv0 + c1 * dv1;
            vd1 += c2 * dv0 + c3 * dv1;
        }
        vs0 += __shfl_xor_sync(0xffffffffu, vs0, 1);
        vs0 += __shfl_xor_sync(0xffffffffu, vs0, 2);
        vs1 += __shfl_xor_sync(0xffffffffu, vs1, 1);
        vs1 += __shfl_xor_sync(0xffffffffu, vs1, 2);
        vd0 += __shfl_xor_sync(0xffffffffu, vd0, 1);
        vd0 += __shfl_xor_sync(0xffffffffu, vd0, 2);
        vd1 += __shfl_xor_sync(0xffffffffu, vd1, 1);
        vd1 += __shfl_xor_sync(0xffffffffu, vd1, 2);
        if ((lane & 3) == 0) {
            g_es[r * NH + head] = vs0;
            g_es[(r + 8) * NH + head] = vs1;
            g_ed[r * NH + head] = vd0;
            g_ed[(r + 8) * NH + head] = vd1;
        }
    }
}

// ---------------- tensor-core fused AGG56 + GCN(56->128) + GAT (layer 0,0) ------
// Also computes g_nsum per dst (sum of norms) for later mas-fused layers.
__global__ __launch_bounds__(256)
void k_fused_mma56(const float* __restrict__ hin,
                   const uint4* __restrict__ wg56, const float* __restrict__ bg,
                   const uint4* __restrict__ wtf,
                   const float* __restrict__ asrc, const float* __restrict__ adst) {
    __shared__ __align__(16) char smraw[64 * HS * 2 * 2];
    float* sAgg = (float*)smraw;                         // 64*64 fp32 = 16384 B
    __nv_bfloat16* sHh = (__nv_bfloat16*)smraw;
    __nv_bfloat16* sHl = (__nv_bfloat16*)(smraw + 64 * HS * 2);
    int tid = threadIdx.x;
    int lane = tid & 31;
    int wid = tid >> 5;
    int n0 = blockIdx.x * 64;

    // ---- agg phase: warp handles 8 dsts sequentially (56-dim) + nsum ----
    {
        int c1 = lane + 32;
        for (int s = 0; s < 8; s++) {
            int dl = wid * 8 + s;
            int d = n0 + dl;
            float a0 = 0.f, a1 = 0.f, ns = 0.f;
            if (d < NN) {
                int e0 = g_off[d], e1v = g_off[d + 1];
                int e = e0;
                for (; e + 2 <= e1v; e += 2) {
                    int s0 = g_srcs[e], s1 = g_srcs[e + 1];
                    float m0 = g_norm[e], m1 = g_norm[e + 1];
                    const float* r0 = hin + s0 * 56;
                    const float* r1 = hin + s1 * 56;
                    a0 += m0 * r0[lane] + m1 * r1[lane];
                    if (c1 < 56) a1 += m0 * r0[c1] + m1 * r1[c1];
                    ns += m0 + m1;
                }
                if (e < e1v) {
                    int s0 = g_srcs[e];
                    float m0 = g_norm[e];
                    const float* r0 = hin + s0 * 56;
                    a0 += m0 * r0[lane];
                    if (c1 < 56) a1 += m0 * r0[c1];
                    ns += m0;
                }
                if (lane == 0) g_nsum[d] = ns;
            }
            sAgg[dl * 64 + lane] = a0;
            sAgg[dl * 64 + c1] = (c1 < 56) ? a1 : 0.f;
        }
    }
    __syncthreads();

    int warp_m = wid & 3;
    int warp_n = wid >> 2;
    int rl = warp_m * 16 + (lane >> 2);
    int r = n0 + rl;
    int kq = (lane & 3) * 2;

    uint32_t ah[4][4], al[4][4];
#pragma unroll
    for (int kc = 0; kc < 4; kc++) {
        const float* ap = sAgg + rl * 64 + kc * 16;
        float2 a00 = *(const float2*)(ap + kq);
        float2 a10 = *(const float2*)(ap + 8 * 64 + kq);
        float2 a02 = *(const float2*)(ap + kq + 8);
        float2 a12 = *(const float2*)(ap + 8 * 64 + kq + 8);
        ah[kc][0] = pkbf2(a00.y, a00.x); al[kc][0] = pkbf2(bfres(a00.y), bfres(a00.x));
        ah[kc][1] = pkbf2(a10.y, a10.x); al[kc][1] = pkbf2(bfres(a10.y), bfres(a10.x));
        ah[kc][2] = pkbf2(a02.y, a02.x); al[kc][2] = pkbf2(bfres(a02.y), bfres(a02.x));
        ah[kc][3] = pkbf2(a12.y, a12.x); al[kc][3] = pkbf2(bfres(a12.y), bfres(a12.x));
    }
    __syncthreads();   // sAgg dead; smem becomes sHh/sHl

    float acc[8][4];
#pragma unroll
    for (int t = 0; t < 8; t++)
        acc[t][0] = acc[t][1] = acc[t][2] = acc[t][3] = 0.f;
#pragma unroll
    for (int kc = 0; kc < 4; kc++) {
        const uint4* wp = wg56 + kc * 16 * 32;
#pragma unroll
        for (int t = 0; t < 8; t++) {
            uint4 b = wp[(warp_n * 8 + t) * 32 + lane];
            mma16816(acc[t], ah[kc], b.x, b.y);
            mma16816(acc[t], ah[kc], b.z, b.w);
            mma16816(acc[t], al[kc], b.x, b.y);
        }
    }

#pragma unroll
    for (int t = 0; t < 8; t++) {
        int c = warp_n * 64 + t * 8 + kq;
        float b0 = bg[c], b1 = bg[c + 1];
        float v0 = fmaxf(acc[t][0] + b0, 0.f), v1 = fmaxf(acc[t][1] + b1, 0.f);
        float v2 = fmaxf(acc[t][2] + b0, 0.f), v3 = fmaxf(acc[t][3] + b1, 0.f);
        int ro = rl * HS + c;
        *(uint32_t*)&sHh[ro] = pkbf2(v1, v0);
        *(uint32_t*)&sHl[ro] = pkbf2(bfres(v1), bfres(v0));
        *(uint32_t*)&sHh[ro + 8 * HS] = pkbf2(v3, v2);
        *(uint32_t*)&sHl[ro + 8 * HS] = pkbf2(bfres(v3), bfres(v2));
    }
    __syncthreads();

#pragma unroll
    for (int t = 0; t < 8; t++)
        acc[t][0] = acc[t][1] = acc[t][2] = acc[t][3] = 0.f;
    uint32_t baseHh = (uint32_t)__cvta_generic_to_shared(sHh);
    uint32_t baseHl = (uint32_t)__cvta_generic_to_shared(sHl);
    int arow = warp_m * 16 + (lane & 15);
#pragma unroll
    for (int kc = 0; kc < 8; kc++) {
        int acol = kc * 16 + (lane >> 4) * 8;
        uint32_t off = (arow * HS + acol) * 2;
        uint32_t a2h[4], a2l[4];
        ldm_x4(a2h[0], a2h[1], a2h[2], a2h[3], baseHh + off);
        ldm_x4(a2l[0], a2l[1], a2l[2], a2l[3], baseHl + off);
        const uint4* wp = wtf + kc * 16 * 32;
#pragma unroll
        for (int t = 0; t < 8; t++) {
            uint4 b = wp[(warp_n * 8 + t) * 32 + lane];
            mma16816(acc[t], a2h, b.x, b.y);
            mma16816(acc[t], a2h, b.z, b.w);
            mma16816(acc[t], a2l, b.x, b.y);
        }
    }

    float* row0p = g_x2 + r * 128;
    float* row1p = g_x2 + (r + 8) * 128;
#pragma unroll
    for (int h2 = 0; h2 < 4; h2++) {
        int head = warp_n * 4 + h2;
        float vs0 = 0.f, vs1 = 0.f, vd0 = 0.f, vd1 = 0.f;
#pragma unroll
        for (int q = 0; q < 2; q++) {
            int t = 2 * h2 + q;
            int c = warp_n * 64 + t * 8 + kq;
            float av0 = asrc[c], av1 = asrc[c + 1];
            float dv0 = adst[c], dv1 = adst[c + 1];
            float c0 = acc[t][0], c1 = acc[t][1], c2 = acc[t][2], c3 = acc[t][3];
            *(float2*)(row0p + c) = make_float2(c0, c1);
            *(float2*)(row1p + c) = make_float2(c2, c3);
            vs0 += c0 * av0 + c1 * av1;
            vs1 += c2 * av0 + c3 * av1;
            vd0 += c0 * dv0 + c1 * dv1;
            vd1 += c2 * dv0 + c3 * dv1;
        }
        vs0 += __shfl_xor_sync(0xffffffffu, vs0, 1);
        vs0 += __shfl_xor_sync(0xffffffffu, vs0, 2);
        vs1 += __shfl_xor_sync(0xffffffffu, vs1, 1);
        vs1 += __shfl_xor_sync(0xffffffffu, vs1, 2);
        vd0 += __shfl_xor_sync(0xffffffffu, vd0, 1);
        vd0 += __shfl_xor_sync(0xffffffffu, vd0, 2);
        vd1 += __shfl_xor_sync(0xffffffffu, vd1, 1);
        vd1 += __shfl_xor_sync(0xffffffffu, vd1, 2);
        if ((lane & 3) == 0) {
            g_es[r * NH + head] = vs0;
            g_es[(r + 8) * NH + head] = vs1;
            g_ed[r * NH + head] = vd0;
            g_ed[(r + 8) * NH + head] = vd1;
        }
    }
}

// ---------------- single-pass GAT edge aggregation (pipelined loads) -------------
// last!=0: fold MAS3+output head (out = hA @ g_fw + g_fb) instead of writing hA.
__global__ void k_gat_edge(const float* __restrict__ gb, float* __restrict__ outp,
                           int last) {
    int w = (blockIdx.x * blockDim.x + threadIdx.x) >> 5;
    int lane = threadIdx.x & 31;
    if (w >= NN) return;
    int h8 = lane & 7;
    int eg = lane >> 3;
    int hsel = lane >> 2;
    float edh = g_ed[w * NH + h8];
    int e0 = g_off[w], e1 = g_off[w + 1];
    unsigned long long acc01 = 0ull, acc23 = 0ull;
    float dsum = 0.f;
    // prologue: load first group's srcs + es
    int ee0 = e0 + eg;
    int idx0 = ee0 < e1 ? ee0 : e1 - 1;
    int soff = g_srcs[idx0] << 7;
    float esv = g_es[(soff >> 4) + h8];
    bool valid = ee0 < e1;
    for (int e = e0; e < e1; e += 4) {
        // prefetch next group (flies under this group's gathers)
        int soff_n = 0;
        float esv_n = 0.f;
        bool valid_n = false;
        int en = e + 4;
        if (en < e1) {
            int een = en + eg;
            int idxn = een < e1 ? een : e1 - 1;
            soff_n = g_srcs[idxn] << 7;
            esv_n = g_es[(soff_n >> 4) + h8];
            valid_n = een < e1;
        }
        float v = esv + edh;
        v = fmaxf(v, 0.2f * v);
        float wv = valid ? __expf(v) : 0.f;
        dsum += wv;
#pragma unroll
        for (int q = 0; q < 4; q++) {
            float wb = __shfl_sync(0xffffffffu, wv, q * 8 + hsel);
            int so = __shfl_sync(0xffffffffu, soff, q * 8);
            unsigned long long wb2;
            PACKW(wb2, wb);
            ulonglong2 hv = reinterpret_cast<const ulonglong2*>(g_x2 + so)[lane];
            FFMA2(acc01, hv.x, wb2);
            FFMA2(acc23, hv.y, wb2);
        }
        soff = soff_n;
        esv = esv_n;
        valid = valid_n;
    }
    dsum += __shfl_xor_sync(0xffffffffu, dsum, 8);
    dsum += __shfl_xor_sync(0xffffffffu, dsum, 16);
    float db = __shfl_sync(0xffffffffu, dsum, hsel);
    float inv = 1.f / db;
    float4 acc;
    UNPK(acc.x, acc.y, acc01);
    UNPK(acc.z, acc.w, acc23);
    acc.x *= inv; acc.y *= inv; acc.z *= inv; acc.w *= inv;
#pragma unroll
    for (int off = 4; off <= 16; off <<= 1) {
        acc.x += __shfl_xor_sync(0xffffffffu, acc.x, off);
        acc.y += __shfl_xor_sync(0xffffffffu, acc.y, off);
        acc.z += __shfl_xor_sync(0xffffffffu, acc.z, off);
        acc.w += __shfl_xor_sync(0xffffffffu, acc.w, off);
    }
    // all lanes in group (lane&3) hold the head-summed value; compute hA channels
    float4 gb4 = reinterpret_cast<const float4*>(gb)[lane & 3];
    float4 r;
    r.x = acc.x * 0.125f + gb4.x;
    r.y = acc.y * 0.125f + gb4.y;
    r.z = acc.z * 0.125f + gb4.z;
    r.w = acc.w * 0.125f + gb4.w;
    if (!last) {
        if (lane < 4)
            reinterpret_cast<float4*>(g_hA + w * PH)[lane] = r;
    } else {
        // broadcast all 16 hA channels, then lanes 0..6 compute output classes
        float hv[16];
#pragma unroll
        for (int l = 0; l < 4; l++) {
            hv[4 * l + 0] = __shfl_sync(0xffffffffu, r.x, l);
            hv[4 * l + 1] = __shfl_sync(0xffffffffu, r.y, l);
            hv[4 * l + 2] = __shfl_sync(0xffffffffu, r.z, l);
            hv[4 * l + 3] = __shfl_sync(0xffffffffu, r.w, l);
        }
        if (lane < NC) {
            float a = g_fb[lane];
#pragma unroll
            for (int k = 0; k < 16; k++) a += hv[k] * g_fw[k * NC + lane];
            outp[w * NC + lane] = a;
        }
    }
}

// ---------------- launcher ----------------
extern "C" void kernel_launch(void* const* d_in, const int* in_sizes, int n_in,
                              void* d_out, int out_size) {
    const float* x      = (const float*)d_in[0];
    const int*   ei     = (const int*)d_in[1];
    const float* w_feat = (const float*)d_in[2];
    const float* b_feat = (const float*)d_in[3];
    const float* gcn0_w = (const float*)d_in[4];
    const float* gcn0_b = (const float*)d_in[5];
    const float* gcn_w  = (const float*)d_in[6];
    const float* gcn_b  = (const float*)d_in[7];
    const float* gat_w  = (const float*)d_in[8];
    const float* gat_as = (const float*)d_in[9];
    const float* gat_ad = (const float*)d_in[10];
    const float* gat_b  = (const float*)d_in[11];
    const float* mas_w  = (const float*)d_in[12];
    const float* mas_b  = (const float*)d_in[13];
    const float* out_w  = (const float*)d_in[14];
    const float* out_b  = (const float*)d_in[15];
    float* out = (float*)d_out;
    (void)in_sizes; (void)n_in; (void)out_size;

    float *p_x1, *p_hA, *p_hB, *p_bvec;
    uint4 *p_wtf, *p_wgf, *p_wg56;
    cudaGetSymbolAddress((void**)&p_x1, g_x1);
    cudaGetSymbolAddress((void**)&p_hA, g_hA);
    cudaGetSymbolAddress((void**)&p_hB, g_hB);
    cudaGetSymbolAddress((void**)&p_bvec, g_bvec);
    cudaGetSymbolAddress((void**)&p_wtf, g_wtf);
    cudaGetSymbolAddress((void**)&p_wgf, g_wgf);
    cudaGetSymbolAddress((void**)&p_wg56, g_wg56);

    // weights prep + CSR build; gemm0 at capture slot #4
    k_deg_count<<<(EE + 255) / 256, 256>>>(ei);
    k_swz<<<(9 * 8 * 128 + 6 * 128 + KC0 * 56 + 4 * 128 + NC + 255) / 256, 256>>>(
        gat_w, gcn_w, w_feat, gcn0_w,
        mas_w + 2 * PH * D0, mas_b + 2 * D0, out_w, out_b);
    k_prep<<<2, 128>>>(mas_w, mas_b, gcn0_w);
    k_gemm0<<<(NN + 127) / 128, 256>>>(x);
    k_scan1<<<NB_SCAN, 256>>>();
    k_scan3<<<NB_SCAN, 256>>>();
    k_fill<<<(ENT + 255) / 256, 256>>>(ei);

    // GNFE: aggregate transformed features (+bias, relu)
    k_agg56<<<NPAD / 8, 256>>>(p_x1, p_hB, b_feat, 1);

    for (int m = 0; m < NL; m++) {
        for (int i = 0; i < NL; i++) {
            int li = m * NL + i;
            const float* as = gat_as + li * NH * PH;
            const float* ad = gat_ad + li * NH * PH;
            const uint4* wtf = p_wtf + li * 8 * 16 * 32;
            if (i == 0 && m == 0) {
                k_fused_mma56<<<NPAD / 64, 256>>>(p_hB, p_wg56, gcn0_b, wtf, as, ad);
            } else if (i == 0) {
                k_fused_mma<<<NPAD / 64, 256>>>(p_hA, p_wgf + li * 16 * 32,
                                                gcn0_b + m * DH,
                                                p_bvec + (m - 1) * DH, wtf, as, ad);
            } else {
                k_fused_mma<<<NPAD / 64, 256>>>(
                    p_hA, p_wgf + li * 16 * 32,
                    gcn_b + (m * (NL - 1) + (i - 1)) * DH,
                    (const float*)0, wtf, as, ad);
            }
            k_gat_edge<<<(NN * 32 + 255) / 256, 256>>>(gat_b + li * PH, out,
                                                       li == 8 ? 1 : 0);
        }
    }
}